// round 12
// baseline (speedup 1.0000x reference)
#include <cuda_runtime.h>
#include <math.h>
#include <stdint.h>

#define NN 50000
#define EE 400000
#define DD 128
#define HH 8
#define CC 16
#define EH 64
#define LL 6

static_assert(EE % 128 == 0, "edge tiling");
static_assert(NN % 8 == 0, "node tiling");

typedef unsigned long long u64;

// ---------------- device scratch (static; no allocations allowed) ----------------
__device__ __align__(16) float g_h  [NN * DD];   // node features
__device__ __align__(16) float g_xl [NN * DD];   // lin_l output (fp32)
__device__ __align__(16) float g_xr [NN * DD];   // lin_r output (fp32)
__device__ __align__(8) uint32_t g_xlh[NN * 64]; // bf16x2 mirror of xl (for passA)
__device__ __align__(8) uint32_t g_xrh[NN * 64]; // bf16x2 mirror of xr (for passA)
__device__ __align__(16) u64 g_ef2[EE * 32];     // ef in CSR-slot order, paired tf32
__device__             float g_a   [EE * HH];    // exp(logit), indexed by CSR SLOT
// CSR by destination node (built once per launch)
__device__ int  g_cnt   [NN];
__device__ int  g_wptr  [NN];
__device__ int  g_rowptr[NN + 1];
__device__ int2 g_csr    [EE];   // (orig edge id, src node) per slot
__device__ int  g_csr_dst[EE];   // dst node per slot
__device__ int  g_slot   [EE];   // edge id -> CSR slot (inverse map)

__device__ __forceinline__ float warp_sum(float v) {
#pragma unroll
    for (int o = 16; o; o >>= 1) v += __shfl_xor_sync(0xffffffffu, v, o);
    return v;
}
__device__ __forceinline__ uint32_t to_tf32(float f) {
    uint32_t t; asm("cvt.rna.tf32.f32 %0, %1;" : "=r"(t) : "f"(f)); return t;
}
__device__ __forceinline__ u64 pack2u(uint32_t lo, uint32_t hi) {
    return ((u64)hi << 32) | (u64)lo;
}
__device__ __forceinline__ uint32_t pack_bf2(float lo, float hi) {
    uint32_t r;
    asm("cvt.rn.bf16x2.f32 %0, %1, %2;" : "=r"(r) : "f"(hi), "f"(lo));
    return r;
}
__device__ __forceinline__ float2 unpack_bf2(uint32_t u) {
    float2 r;
    r.x = __uint_as_float(u << 16);
    r.y = __uint_as_float(u & 0xffff0000u);
    return r;
}

// ---------------- node encoder: x(N,9) -> LN -> relu -> g_h(N,128). 1 warp/node ----
__global__ void node_enc_kernel(const float* __restrict__ x,
                                const float* __restrict__ W,
                                const float* __restrict__ b,
                                const float* __restrict__ g,
                                const float* __restrict__ beta) {
    int warp = (blockIdx.x * blockDim.x + threadIdx.x) >> 5;
    int lane = threadIdx.x & 31;
    if (warp >= NN) return;
    float acc[4];
#pragma unroll
    for (int j = 0; j < 4; j++) acc[j] = b[lane + 32 * j];
#pragma unroll
    for (int k = 0; k < 9; k++) {
        float xv = x[warp * 9 + k];
#pragma unroll
        for (int j = 0; j < 4; j++) acc[j] += xv * W[k * DD + lane + 32 * j];
    }
    float s = 0.f;
#pragma unroll
    for (int j = 0; j < 4; j++) s += acc[j];
    float m = warp_sum(s) * (1.0f / DD);
    float v = 0.f;
#pragma unroll
    for (int j = 0; j < 4; j++) { float d = acc[j] - m; v += d * d; }
    v = warp_sum(v) * (1.0f / DD);
    float rstd = rsqrtf(v + 1e-5f);
#pragma unroll
    for (int j = 0; j < 4; j++) {
        int d = lane + 32 * j;
        float y = (acc[j] - m) * rstd * g[d] + beta[d];
        g_h[warp * DD + d] = fmaxf(y, 0.0f);
    }
}

// ---------------- edge encoder -> g_ef2[slot] in paired-tf32 fragment layout -------
// 1 warp/edge. Pair p=lane covers dims (k_lo, k_lo+4), k_lo=(p>>2)*8+(p&3).
__global__ void edge_enc_kernel(const float* __restrict__ ea,
                                const float* __restrict__ W,
                                const float* __restrict__ b,
                                const float* __restrict__ g,
                                const float* __restrict__ beta) {
    int warp = (blockIdx.x * blockDim.x + threadIdx.x) >> 5;
    int lane = threadIdx.x & 31;
    if (warp >= EE) return;
    float a0 = b[lane], a1 = b[lane + 32];
#pragma unroll
    for (int k = 0; k < 3; k++) {
        float xv = ea[warp * 3 + k];
        a0 += xv * W[k * EH + lane];
        a1 += xv * W[k * EH + 32 + lane];
    }
    float m = warp_sum(a0 + a1) * (1.0f / EH);
    float d0 = a0 - m, d1 = a1 - m;
    float v = warp_sum(d0 * d0 + d1 * d1) * (1.0f / EH);
    float rstd = rsqrtf(v + 1e-5f);
    float y0 = fmaxf(d0 * rstd * g[lane] + beta[lane], 0.f);          // dim = lane
    float y1 = fmaxf(d1 * rstd * g[lane + 32] + beta[lane + 32], 0.f); // dim = lane+32

    int k_lo = ((lane >> 2) << 3) + (lane & 3);
    int k_hi = k_lo + 4;
    float la = __shfl_sync(0xffffffffu, y0, k_lo & 31);
    float lb = __shfl_sync(0xffffffffu, y1, k_lo & 31);
    float ha = __shfl_sync(0xffffffffu, y0, k_hi & 31);
    float hb = __shfl_sync(0xffffffffu, y1, k_hi & 31);
    float v_lo = (k_lo < 32) ? la : lb;
    float v_hi = (k_hi < 32) ? ha : hb;
    int slot = g_slot[warp];
    g_ef2[(size_t)slot * 32 + lane] = pack2u(to_tf32(v_lo), to_tf32(v_hi));
}

// ---------------- CSR build (once per launch) --------------------------------------
__global__ void csr_zero_kernel() {
    int i = blockIdx.x * blockDim.x + threadIdx.x;
    if (i < NN) g_cnt[i] = 0;
}
__global__ void csr_count_kernel(const int* __restrict__ ei) {
    int e = blockIdx.x * blockDim.x + threadIdx.x;
    if (e < EE) atomicAdd(&g_cnt[ei[EE + e]], 1);
}
__global__ void csr_scan_kernel() {
    __shared__ int warpsum[32];
    __shared__ int s_total;
    int tid = threadIdx.x, lane = tid & 31, wid = tid >> 5;
    if (tid == 0) { s_total = 0; g_rowptr[0] = 0; }
    __syncthreads();
    for (int base = 0; base < NN; base += 1024) {
        int i = base + tid;
        int v = (i < NN) ? g_cnt[i] : 0;
        int x = v;
#pragma unroll
        for (int o = 1; o < 32; o <<= 1) {
            int t = __shfl_up_sync(0xffffffffu, x, o);
            if (lane >= o) x += t;
        }
        if (lane == 31) warpsum[wid] = x;
        __syncthreads();
        if (wid == 0) {
            int w = warpsum[lane];
#pragma unroll
            for (int o = 1; o < 32; o <<= 1) {
                int t = __shfl_up_sync(0xffffffffu, w, o);
                if (lane >= o) w += t;
            }
            warpsum[lane] = w;
        }
        __syncthreads();
        int incl = s_total + (wid ? warpsum[wid - 1] : 0) + x;
        if (i < NN) {
            g_rowptr[i + 1] = incl;
            g_wptr[i] = incl - v;
        }
        __syncthreads();
        if (tid == 0) s_total += warpsum[31];
        __syncthreads();
    }
}
__global__ void csr_scatter_kernel(const int* __restrict__ ei) {
    int e = blockIdx.x * blockDim.x + threadIdx.x;
    if (e < EE) {
        int d = ei[EE + e];
        int pos = atomicAdd(&g_wptr[d], 1);
        g_csr[pos] = make_int2(e, ei[e]);
        g_csr_dst[pos] = d;
        g_slot[e] = pos;
    }
}

// ---------------- xl/xr GEMM: tf32 tensor cores, 64 rows/block, K=128 --------------
#define LIN_ROWS 64
#define LKS 68   // u64 stride per row: 64 pairs (K=128) + 4 pad
#define LIN_SMEM (LIN_ROWS * LKS * 8 + DD * LKS * 8)
__global__ __launch_bounds__(256, 2) void lin_kernel(
    const float* __restrict__ Wl, const float* __restrict__ bl,
    const float* __restrict__ Wr, const float* __restrict__ br) {
    extern __shared__ char smem_raw[];
    u64* sA = (u64*)smem_raw;                          // [64 rows][LKS] pairs
    u64* sW = (u64*)(smem_raw + LIN_ROWS * LKS * 8);   // [128 n][LKS] pairs
    const float* W  = blockIdx.y ? Wr : Wl;
    const float* bv = blockIdx.y ? br : bl;
    float* dst = blockIdx.y ? g_xr : g_xl;
    uint32_t* dsth = blockIdx.y ? g_xrh : g_xlh;
    int m0 = blockIdx.x * LIN_ROWS;
    int tid = threadIdx.x;

    for (int idx = tid; idx < LIN_ROWS * (DD / 8); idx += 256) {
        int r = idx >> 4, k8 = (idx & 15) << 3;
        int gm = m0 + r;
        float4 v0 = make_float4(0.f, 0.f, 0.f, 0.f), v1 = v0;
        if (gm < NN) {
            v0 = *(const float4*)&g_h[(size_t)gm * DD + k8];
            v1 = *(const float4*)&g_h[(size_t)gm * DD + k8 + 4];
        }
        u64* d = sA + r * LKS + (k8 >> 3) * 4;
        d[0] = pack2u(to_tf32(v0.x), to_tf32(v1.x));
        d[1] = pack2u(to_tf32(v0.y), to_tf32(v1.y));
        d[2] = pack2u(to_tf32(v0.z), to_tf32(v1.z));
        d[3] = pack2u(to_tf32(v0.w), to_tf32(v1.w));
    }
    for (int idx = tid; idx < DD * (DD / 8); idx += 256) {
        int n = idx & 127, k0 = idx >> 7;
        float w[8];
#pragma unroll
        for (int j = 0; j < 8; j++) w[j] = W[(k0 * 8 + j) * DD + n];
#pragma unroll
        for (int j = 0; j < 4; j++)
            sW[n * LKS + k0 * 4 + j] = pack2u(to_tf32(w[j]), to_tf32(w[j + 4]));
    }
    __syncthreads();

    int lane = tid & 31, wm = tid >> 5;
    int gid = lane >> 2, q = lane & 3;
    int row_base = (wm & 3) * 16;
    int n_base = (wm >> 2) * 64;
    int r0 = row_base + gid, r1 = r0 + 8;
    const u64* ar0 = sA + r0 * LKS;
    const u64* ar1 = sA + r1 * LKS;

    float d[8][4];
#pragma unroll
    for (int n8 = 0; n8 < 8; n8++)
#pragma unroll
        for (int j = 0; j < 4; j++) d[n8][j] = 0.f;

#pragma unroll
    for (int k0 = 0; k0 < 16; k0++) {
        u64 pa0 = ar0[k0 * 4 + q];
        u64 pa1 = ar1[k0 * 4 + q];
        uint32_t a0 = (uint32_t)pa0, a2 = (uint32_t)(pa0 >> 32);
        uint32_t a1 = (uint32_t)pa1, a3 = (uint32_t)(pa1 >> 32);
#pragma unroll
        for (int n8 = 0; n8 < 8; n8++) {
            u64 pb = sW[(n_base + n8 * 8 + gid) * LKS + k0 * 4 + q];
            uint32_t b0 = (uint32_t)pb, b1 = (uint32_t)(pb >> 32);
            asm volatile(
                "mma.sync.aligned.m16n8k8.row.col.f32.tf32.tf32.f32 "
                "{%0,%1,%2,%3}, {%4,%5,%6,%7}, {%8,%9}, {%0,%1,%2,%3};"
                : "+f"(d[n8][0]), "+f"(d[n8][1]), "+f"(d[n8][2]), "+f"(d[n8][3])
                : "r"(a0), "r"(a1), "r"(a2), "r"(a3), "r"(b0), "r"(b1));
        }
    }

    int gm0 = m0 + r0, gm1 = m0 + r1;
#pragma unroll
    for (int n8 = 0; n8 < 8; n8++) {
        int c = n_base + n8 * 8 + 2 * q;
        float2 bb = *(const float2*)&bv[c];
        if (gm0 < NN) {
            float2 o = make_float2(d[n8][0] + bb.x, d[n8][1] + bb.y);
            *(float2*)&dst[(size_t)gm0 * DD + c] = o;
            dsth[(size_t)gm0 * 64 + (c >> 1)] = pack_bf2(o.x, o.y);
        }
        if (gm1 < NN) {
            float2 o = make_float2(d[n8][2] + bb.x, d[n8][3] + bb.y);
            *(float2*)&dst[(size_t)gm1 * DD + c] = o;
            dsth[(size_t)gm1 * 64 + (c >> 1)] = pack_bf2(o.x, o.y);
        }
    }
}

// ---------------- pass A: tf32 TC ee GEMM; ef staged by pure linear u64 copy -------
#define PA_EDGES 128
#define EFS2 36   // u64 stride per row: 32 pairs + 4 pad
#define PASSA_SMEM (PA_EDGES * EFS2 * 8 + DD * EFS2 * 8 + DD * 4)
__global__ __launch_bounds__(256, 3) void passA_kernel(const float* __restrict__ We,
                                                       const float* __restrict__ att) {
    extern __shared__ char smem_raw[];
    u64*   sEf2 = (u64*)smem_raw;                            // [128 rows][EFS2] pairs
    u64*   sWe2 = (u64*)(smem_raw + PA_EDGES * EFS2 * 8);    // [128 n][EFS2] pairs
    float* sAtt = (float*)(smem_raw + PA_EDGES * EFS2 * 8 + DD * EFS2 * 8);
    __shared__ int sSrc[PA_EDGES], sDst[PA_EDGES];
    int tid = threadIdx.x;
    int eb = blockIdx.x * PA_EDGES;

    if (tid < PA_EDGES) {
        sSrc[tid] = g_csr[eb + tid].y;
        sDst[tid] = g_csr_dst[eb + tid];
    }
    if (tid < DD) sAtt[tid] = att[tid];
    // stage We as paired tf32 (layer weight; unavoidable per block)
    for (int idx = tid; idx < DD * (EH / 8); idx += 256) {
        int n = idx & 127, k0 = idx >> 7;
        float w[8];
#pragma unroll
        for (int j = 0; j < 8; j++) w[j] = We[(k0 * 8 + j) * DD + n];
#pragma unroll
        for (int j = 0; j < 4; j++)
            sWe2[n * EFS2 + k0 * 4 + j] = pack2u(to_tf32(w[j]), to_tf32(w[j + 4]));
    }
    // stage ef tile: PURE linear uint4 copy from pre-permuted, pre-converted g_ef2
    for (int idx = tid; idx < PA_EDGES * 16; idx += 256) {
        int r = idx >> 4, c2 = (idx & 15) << 1;
        uint4 v = *(const uint4*)&g_ef2[(size_t)(eb + r) * 32 + c2];
        *(uint4*)&sEf2[r * EFS2 + c2] = v;
    }
    __syncthreads();

    int lane = tid & 31, wm = tid >> 5;
    int gid = lane >> 2, q = lane & 3;

    int r0 = wm * 16 + gid;
    int r1 = r0 + 8;
    const uint32_t* xl0h = g_xlh + (size_t)sSrc[r0] * 64;
    const uint32_t* xr0h = g_xrh + (size_t)sDst[r0] * 64;
    const uint32_t* xl1h = g_xlh + (size_t)sSrc[r1] * 64;
    const uint32_t* xr1h = g_xrh + (size_t)sDst[r1] * 64;
    const u64* efr0 = sEf2 + r0 * EFS2;
    const u64* efr1 = sEf2 + r1 * EFS2;

    float h0[8], h1[8];
#pragma unroll
    for (int h = 0; h < 8; h++) { h0[h] = 0.f; h1[h] = 0.f; }

#pragma unroll
    for (int half = 0; half < 2; half++) {
        float d[8][4];
#pragma unroll
        for (int n8 = 0; n8 < 8; n8++)
#pragma unroll
            for (int j = 0; j < 4; j++) d[n8][j] = 0.f;

#pragma unroll
        for (int k0 = 0; k0 < 8; k0++) {
            u64 pa0 = efr0[k0 * 4 + q];
            u64 pa1 = efr1[k0 * 4 + q];
            uint32_t a0 = (uint32_t)pa0, a2 = (uint32_t)(pa0 >> 32);
            uint32_t a1 = (uint32_t)pa1, a3 = (uint32_t)(pa1 >> 32);
#pragma unroll
            for (int n8 = 0; n8 < 8; n8++) {
                int n = half * 8 + n8;
                u64 pb = sWe2[(n * 8 + gid) * EFS2 + k0 * 4 + q];
                uint32_t b0 = (uint32_t)pb, b1 = (uint32_t)(pb >> 32);
                asm volatile(
                    "mma.sync.aligned.m16n8k8.row.col.f32.tf32.tf32.f32 "
                    "{%0,%1,%2,%3}, {%4,%5,%6,%7}, {%8,%9}, {%0,%1,%2,%3};"
                    : "+f"(d[n8][0]), "+f"(d[n8][1]), "+f"(d[n8][2]), "+f"(d[n8][3])
                    : "r"(a0), "r"(a1), "r"(a2), "r"(a3), "r"(b0), "r"(b1));
            }
        }
#pragma unroll
        for (int n8 = 0; n8 < 8; n8++) {
            int n = half * 8 + n8;
            int ci = n * 4 + q;
            float2 av = *(const float2*)&sAtt[n * 8 + q * 2];
            float2 l0v = unpack_bf2(xl0h[ci]);
            float2 r0v = unpack_bf2(xr0h[ci]);
            float2 l1v = unpack_bf2(xl1h[ci]);
            float2 r1v = unpack_bf2(xr1h[ci]);
            float v00 = d[n8][0] + l0v.x + r0v.x; v00 = v00 > 0.f ? v00 : 0.2f * v00;
            float v01 = d[n8][1] + l0v.y + r0v.y; v01 = v01 > 0.f ? v01 : 0.2f * v01;
            float v10 = d[n8][2] + l1v.x + r1v.x; v10 = v10 > 0.f ? v10 : 0.2f * v10;
            float v11 = d[n8][3] + l1v.y + r1v.y; v11 = v11 > 0.f ? v11 : 0.2f * v11;
            h0[n >> 1] += v00 * av.x + v01 * av.y;
            h1[n >> 1] += v10 * av.x + v11 * av.y;
        }
    }
#pragma unroll
    for (int h = 0; h < 8; h++) {
        h0[h] += __shfl_xor_sync(0xffffffffu, h0[h], 1);
        h0[h] += __shfl_xor_sync(0xffffffffu, h0[h], 2);
        h1[h] += __shfl_xor_sync(0xffffffffu, h1[h], 1);
        h1[h] += __shfl_xor_sync(0xffffffffu, h1[h], 2);
    }
    size_t p0 = (size_t)(eb + r0) * HH;
    size_t p1 = (size_t)(eb + r1) * HH;
    g_a[p0 + 2 * q]     = expf(h0[2 * q]);
    g_a[p0 + 2 * q + 1] = expf(h0[2 * q + 1]);
    g_a[p1 + 2 * q]     = expf(h1[2 * q]);
    g_a[p1 + 2 * q + 1] = expf(h1[2 * q + 1]);
}

// ---------------- pass B: per-dst gather (no atomics) + fused residual+LN+relu -----
__global__ void passB_kernel(const float* __restrict__ cb,
                             const float* __restrict__ g,
                             const float* __restrict__ beta) {
    int node = (blockIdx.x * blockDim.x + threadIdx.x) >> 5;
    int lane = threadIdx.x & 31;
    if (node >= NN) return;
    int start = g_rowptr[node], end = g_rowptr[node + 1];

    float s = 0.f;
    for (int p0 = start; p0 < end; p0 += 4) {
        int p = p0 + (lane >> 3);
        if (p < end) s += g_a[(size_t)p * HH + (lane & 7)];
    }
    s += __shfl_xor_sync(0xffffffffu, s, 8);
    s += __shfl_xor_sync(0xffffffffu, s, 16);
    float sh = __shfl_sync(0xffffffffu, s, lane >> 2);
    float rinv = 1.0f / (sh + 1e-16f);

    int head = lane >> 2;
    float4 acc = make_float4(0.f, 0.f, 0.f, 0.f);
    int p = start;
    for (; p + 4 <= end; p += 4) {
        int s0 = g_csr[p].y,     s1 = g_csr[p + 1].y;
        int s2 = g_csr[p + 2].y, s3 = g_csr[p + 3].y;
        float a0 = g_a[(size_t)(p)     * HH + head];
        float a1 = g_a[(size_t)(p + 1) * HH + head];
        float a2 = g_a[(size_t)(p + 2) * HH + head];
        float a3 = g_a[(size_t)(p + 3) * HH + head];
        float4 x0 = *(const float4*)&g_xl[(size_t)s0 * DD + 4 * lane];
        float4 x1 = *(const float4*)&g_xl[(size_t)s1 * DD + 4 * lane];
        float4 x2 = *(const float4*)&g_xl[(size_t)s2 * DD + 4 * lane];
        float4 x3 = *(const float4*)&g_xl[(size_t)s3 * DD + 4 * lane];
        acc.x += a0 * x0.x + a1 * x1.x + a2 * x2.x + a3 * x3.x;
        acc.y += a0 * x0.y + a1 * x1.y + a2 * x2.y + a3 * x3.y;
        acc.z += a0 * x0.z + a1 * x1.z + a2 * x2.z + a3 * x3.z;
        acc.w += a0 * x0.w + a1 * x1.w + a2 * x2.w + a3 * x3.w;
    }
    for (; p < end; p++) {
        int sn = g_csr[p].y;
        float al = g_a[(size_t)p * HH + head];
        float4 xv = *(const float4*)&g_xl[(size_t)sn * DD + 4 * lane];
        acc.x += al * xv.x; acc.y += al * xv.y;
        acc.z += al * xv.z; acc.w += al * xv.w;
    }
    acc.x *= rinv; acc.y *= rinv; acc.z *= rinv; acc.w *= rinv;

    int d0 = 4 * lane;
    float4 hv = *(const float4*)&g_h[node * DD + d0];
    float4 cv = *(const float4*)&cb[d0];
    float a0 = acc.x + cv.x + hv.x;
    float a1 = acc.y + cv.y + hv.y;
    float a2 = acc.z + cv.z + hv.z;
    float a3 = acc.w + cv.w + hv.w;
    float m = warp_sum(a0 + a1 + a2 + a3) * (1.0f / DD);
    float e0d = a0 - m, e1d = a1 - m, e2d = a2 - m, e3d = a3 - m;
    float v = warp_sum(e0d * e0d + e1d * e1d + e2d * e2d + e3d * e3d) * (1.0f / DD);
    float rstd = rsqrtf(v + 1e-5f);
    float4 gv = *(const float4*)&g[d0];
    float4 bv = *(const float4*)&beta[d0];
    float4 o;
    o.x = fmaxf(e0d * rstd * gv.x + bv.x, 0.f);
    o.y = fmaxf(e1d * rstd * gv.y + bv.y, 0.f);
    o.z = fmaxf(e2d * rstd * gv.z + bv.z, 0.f);
    o.w = fmaxf(e3d * rstd * gv.w + bv.w, 0.f);
    *(float4*)&g_h[node * DD + d0] = o;
}

// ---------------- head: relu(h@W1+b1) @ W2 -> sigmoid. 1 warp/node -----------------
__global__ void head_kernel(float* __restrict__ out,
                            const float* __restrict__ W1, const float* __restrict__ b1,
                            const float* __restrict__ W2, const float* __restrict__ b2) {
    int warp = (blockIdx.x * blockDim.x + threadIdx.x) >> 5;
    int lane = threadIdx.x & 31;
    if (warp >= NN) return;
    float hr[4];
#pragma unroll
    for (int q = 0; q < 4; q++) hr[q] = g_h[warp * DD + q * 32 + lane];
    float z0 = b1[lane], z1 = b1[lane + 32];
#pragma unroll
    for (int q = 0; q < 4; q++) {
#pragma unroll 8
        for (int kk = 0; kk < 32; kk++) {
            float hk = __shfl_sync(0xffffffffu, hr[q], kk);
            int k = q * 32 + kk;
            z0 += hk * W1[k * 64 + lane];
            z1 += hk * W1[k * 64 + 32 + lane];
        }
    }
    z0 = fmaxf(z0, 0.f);
    z1 = fmaxf(z1, 0.f);
    float p = z0 * W2[lane] + z1 * W2[lane + 32];
    p = warp_sum(p);
    if (lane == 0) out[warp] = 1.0f / (1.0f + expf(-(p + b2[0])));
}

// ---------------- launch ----------------------------------------------------------
extern "C" void kernel_launch(void* const* d_in, const int* in_sizes, int n_in,
                              void* d_out, int out_size) {
    const float* x    = (const float*)d_in[0];
    const int*   ei   = (const int*)  d_in[1];
    const float* ea   = (const float*)d_in[2];
    const float* neW  = (const float*)d_in[3];
    const float* neb  = (const float*)d_in[4];
    const float* neg  = (const float*)d_in[5];
    const float* nebt = (const float*)d_in[6];
    const float* eeW  = (const float*)d_in[7];
    const float* eeb  = (const float*)d_in[8];
    const float* eeg  = (const float*)d_in[9];
    const float* eebt = (const float*)d_in[10];
    const float* Wl   = (const float*)d_in[11];
    const float* bl   = (const float*)d_in[12];
    const float* Wr   = (const float*)d_in[13];
    const float* br   = (const float*)d_in[14];
    const float* We   = (const float*)d_in[15];
    const float* att  = (const float*)d_in[16];
    const float* cb   = (const float*)d_in[17];
    const float* lng  = (const float*)d_in[18];
    const float* lnb  = (const float*)d_in[19];
    const float* W1   = (const float*)d_in[20];
    const float* b1   = (const float*)d_in[21];
    const float* W2   = (const float*)d_in[22];
    const float* b2   = (const float*)d_in[23];
    float* out = (float*)d_out;

    cudaFuncSetAttribute(lin_kernel, cudaFuncAttributeMaxDynamicSharedMemorySize,
                         LIN_SMEM);
    cudaFuncSetAttribute(passA_kernel, cudaFuncAttributeMaxDynamicSharedMemorySize,
                         PASSA_SMEM);

    dim3 lin_grid((NN + LIN_ROWS - 1) / LIN_ROWS, 2);
    int passa_grid = EE / PA_EDGES;

    node_enc_kernel<<<NN / 8, 256>>>(x, neW, neb, neg, nebt);                    // 0
    csr_zero_kernel<<<(NN + 255) / 256, 256>>>();                                // 1
    csr_count_kernel<<<(EE + 255) / 256, 256>>>(ei);                             // 2
    lin_kernel<<<lin_grid, 256, LIN_SMEM>>>(Wl, bl, Wr, br);                     // 3 (profiled; control)
    csr_scan_kernel<<<1, 1024>>>();                                              // 4
    csr_scatter_kernel<<<(EE + 255) / 256, 256>>>(ei);                           // 5
    edge_enc_kernel<<<EE / 8, 256>>>(ea, eeW, eeb, eeg, eebt);                   // 6 (needs g_slot)

    for (int l = 0; l < LL; l++) {
        if (l > 0)
            lin_kernel<<<lin_grid, 256, LIN_SMEM>>>(Wl + l * DD * DD, bl + l * DD,
                                                    Wr + l * DD * DD, br + l * DD);
        passA_kernel<<<passa_grid, 256, PASSA_SMEM>>>(We + l * EH * DD,
                                                      att + l * HH * CC);
        passB_kernel<<<(NN * 32 + 255) / 256, 256>>>(cb + l * DD, lng + l * DD,
                                                     lnb + l * DD);
    }
    head_kernel<<<NN / 8, 256>>>(out, W1, b1, W2, b2);
}

// round 13
// speedup vs baseline: 1.2197x; 1.2197x over previous
#include <cuda_runtime.h>
#include <math.h>
#include <stdint.h>

#define NN 50000
#define EE 400000
#define DD 128
#define HH 8
#define CC 16
#define EH 64
#define LL 6

static_assert(EE % 128 == 0, "edge tiling");
static_assert(NN % 8 == 0, "node tiling");

typedef unsigned long long u64;

// ---------------- device scratch (static; no allocations allowed) ----------------
__device__ __align__(16) float g_h  [NN * DD];   // node features
__device__ __align__(16) float g_xl [NN * DD];   // lin_l output (fp32)
__device__ __align__(16) float g_xr [NN * DD];   // lin_r output (fp32)
__device__ __align__(8) uint32_t g_xlh[NN * 64]; // bf16x2 mirror of xl (for passA)
__device__ __align__(8) uint32_t g_xrh[NN * 64]; // bf16x2 mirror of xr (for passA)
__device__ __align__(16) u64 g_ef2[EE * 16];     // ef, CSR-slot order, bf16 m16n8k16 frags
__device__             float g_a   [EE * HH];    // exp(logit), indexed by CSR SLOT
// CSR by destination node (built once per launch)
__device__ int  g_cnt   [NN];
__device__ int  g_wptr  [NN];
__device__ int  g_rowptr[NN + 1];
__device__ int2 g_csr    [EE];   // (orig edge id, src node) per slot
__device__ int  g_csr_dst[EE];   // dst node per slot
__device__ int  g_slot   [EE];   // edge id -> CSR slot (inverse map)

__device__ __forceinline__ float warp_sum(float v) {
#pragma unroll
    for (int o = 16; o; o >>= 1) v += __shfl_xor_sync(0xffffffffu, v, o);
    return v;
}
__device__ __forceinline__ uint32_t to_tf32(float f) {
    uint32_t t; asm("cvt.rna.tf32.f32 %0, %1;" : "=r"(t) : "f"(f)); return t;
}
__device__ __forceinline__ u64 pack2u(uint32_t lo, uint32_t hi) {
    return ((u64)hi << 32) | (u64)lo;
}
__device__ __forceinline__ uint32_t pack_bf2(float lo, float hi) {
    uint32_t r;
    asm("cvt.rn.bf16x2.f32 %0, %1, %2;" : "=r"(r) : "f"(hi), "f"(lo));
    return r;
}
__device__ __forceinline__ float2 unpack_bf2(uint32_t u) {
    float2 r;
    r.x = __uint_as_float(u << 16);
    r.y = __uint_as_float(u & 0xffff0000u);
    return r;
}

// ---------------- node encoder: x(N,9) -> LN -> relu -> g_h(N,128). 1 warp/node ----
__global__ void node_enc_kernel(const float* __restrict__ x,
                                const float* __restrict__ W,
                                const float* __restrict__ b,
                                const float* __restrict__ g,
                                const float* __restrict__ beta) {
    int warp = (blockIdx.x * blockDim.x + threadIdx.x) >> 5;
    int lane = threadIdx.x & 31;
    if (warp >= NN) return;
    float acc[4];
#pragma unroll
    for (int j = 0; j < 4; j++) acc[j] = b[lane + 32 * j];
#pragma unroll
    for (int k = 0; k < 9; k++) {
        float xv = x[warp * 9 + k];
#pragma unroll
        for (int j = 0; j < 4; j++) acc[j] += xv * W[k * DD + lane + 32 * j];
    }
    float s = 0.f;
#pragma unroll
    for (int j = 0; j < 4; j++) s += acc[j];
    float m = warp_sum(s) * (1.0f / DD);
    float v = 0.f;
#pragma unroll
    for (int j = 0; j < 4; j++) { float d = acc[j] - m; v += d * d; }
    v = warp_sum(v) * (1.0f / DD);
    float rstd = rsqrtf(v + 1e-5f);
#pragma unroll
    for (int j = 0; j < 4; j++) {
        int d = lane + 32 * j;
        float y = (acc[j] - m) * rstd * g[d] + beta[d];
        g_h[warp * DD + d] = fmaxf(y, 0.0f);
    }
}

// ---------------- edge encoder -> g_ef2[slot], bf16 m16n8k16 fragment layout -------
// 1 warp/edge. u64 index L=(g*4+q), L<16: lo = bf16x2(dim 16g+2q, +1),
// hi = bf16x2(dim 16g+2q+8, +9).
__global__ void edge_enc_kernel(const float* __restrict__ ea,
                                const float* __restrict__ W,
                                const float* __restrict__ b,
                                const float* __restrict__ g,
                                const float* __restrict__ beta) {
    int warp = (blockIdx.x * blockDim.x + threadIdx.x) >> 5;
    int lane = threadIdx.x & 31;
    if (warp >= EE) return;
    float a0 = b[lane], a1 = b[lane + 32];
#pragma unroll
    for (int k = 0; k < 3; k++) {
        float xv = ea[warp * 3 + k];
        a0 += xv * W[k * EH + lane];
        a1 += xv * W[k * EH + 32 + lane];
    }
    float m = warp_sum(a0 + a1) * (1.0f / EH);
    float d0v = a0 - m, d1v = a1 - m;
    float v = warp_sum(d0v * d0v + d1v * d1v) * (1.0f / EH);
    float rstd = rsqrtf(v + 1e-5f);
    float y0 = fmaxf(d0v * rstd * g[lane] + beta[lane], 0.f);           // dim = lane
    float y1 = fmaxf(d1v * rstd * g[lane + 32] + beta[lane + 32], 0.f); // dim = lane+32

    int L = lane & 15;
    int gk = L >> 2, q = L & 3;
    int d0 = gk * 16 + 2 * q;        // <= 54
    int d1 = d0 + 1, d2 = d0 + 8, d3 = d0 + 9;   // d3 <= 63
    // value(d) = d < 32 ? y0@lane d : y1@lane d-32  (all lanes execute shfls)
    float s0a = __shfl_sync(0xffffffffu, y0, d0 & 31);
    float s0b = __shfl_sync(0xffffffffu, y1, d0 & 31);
    float s1a = __shfl_sync(0xffffffffu, y0, d1 & 31);
    float s1b = __shfl_sync(0xffffffffu, y1, d1 & 31);
    float s2a = __shfl_sync(0xffffffffu, y0, d2 & 31);
    float s2b = __shfl_sync(0xffffffffu, y1, d2 & 31);
    float s3a = __shfl_sync(0xffffffffu, y0, d3 & 31);
    float s3b = __shfl_sync(0xffffffffu, y1, d3 & 31);
    if (lane < 16) {
        float v0 = (d0 < 32) ? s0a : s0b;
        float v1 = (d1 < 32) ? s1a : s1b;
        float v2 = (d2 < 32) ? s2a : s2b;
        float v3 = (d3 < 32) ? s3a : s3b;
        int slot = g_slot[warp];
        g_ef2[(size_t)slot * 16 + L] =
            pack2u(pack_bf2(v0, v1), pack_bf2(v2, v3));
    }
}

// ---------------- CSR build (once per launch) --------------------------------------
__global__ void csr_zero_kernel() {
    int i = blockIdx.x * blockDim.x + threadIdx.x;
    if (i < NN) g_cnt[i] = 0;
}
__global__ void csr_count_kernel(const int* __restrict__ ei) {
    int e = blockIdx.x * blockDim.x + threadIdx.x;
    if (e < EE) atomicAdd(&g_cnt[ei[EE + e]], 1);
}
__global__ void csr_scan_kernel() {
    __shared__ int warpsum[32];
    __shared__ int s_total;
    int tid = threadIdx.x, lane = tid & 31, wid = tid >> 5;
    if (tid == 0) { s_total = 0; g_rowptr[0] = 0; }
    __syncthreads();
    for (int base = 0; base < NN; base += 1024) {
        int i = base + tid;
        int v = (i < NN) ? g_cnt[i] : 0;
        int x = v;
#pragma unroll
        for (int o = 1; o < 32; o <<= 1) {
            int t = __shfl_up_sync(0xffffffffu, x, o);
            if (lane >= o) x += t;
        }
        if (lane == 31) warpsum[wid] = x;
        __syncthreads();
        if (wid == 0) {
            int w = warpsum[lane];
#pragma unroll
            for (int o = 1; o < 32; o <<= 1) {
                int t = __shfl_up_sync(0xffffffffu, w, o);
                if (lane >= o) w += t;
            }
            warpsum[lane] = w;
        }
        __syncthreads();
        int incl = s_total + (wid ? warpsum[wid - 1] : 0) + x;
        if (i < NN) {
            g_rowptr[i + 1] = incl;
            g_wptr[i] = incl - v;
        }
        __syncthreads();
        if (tid == 0) s_total += warpsum[31];
        __syncthreads();
    }
}
__global__ void csr_scatter_kernel(const int* __restrict__ ei) {
    int e = blockIdx.x * blockDim.x + threadIdx.x;
    if (e < EE) {
        int d = ei[EE + e];
        int pos = atomicAdd(&g_wptr[d], 1);
        g_csr[pos] = make_int2(e, ei[e]);
        g_csr_dst[pos] = d;
        g_slot[e] = pos;
    }
}

// ---------------- xl/xr GEMM: tf32 tensor cores, 64 rows/block, K=128 --------------
#define LIN_ROWS 64
#define LKS 68   // u64 stride per row: 64 pairs (K=128) + 4 pad
#define LIN_SMEM (LIN_ROWS * LKS * 8 + DD * LKS * 8)
__global__ __launch_bounds__(256, 2) void lin_kernel(
    const float* __restrict__ Wl, const float* __restrict__ bl,
    const float* __restrict__ Wr, const float* __restrict__ br) {
    extern __shared__ char smem_raw[];
    u64* sA = (u64*)smem_raw;                          // [64 rows][LKS] pairs
    u64* sW = (u64*)(smem_raw + LIN_ROWS * LKS * 8);   // [128 n][LKS] pairs
    const float* W  = blockIdx.y ? Wr : Wl;
    const float* bv = blockIdx.y ? br : bl;
    float* dst = blockIdx.y ? g_xr : g_xl;
    uint32_t* dsth = blockIdx.y ? g_xrh : g_xlh;
    int m0 = blockIdx.x * LIN_ROWS;
    int tid = threadIdx.x;

    for (int idx = tid; idx < LIN_ROWS * (DD / 8); idx += 256) {
        int r = idx >> 4, k8 = (idx & 15) << 3;
        int gm = m0 + r;
        float4 v0 = make_float4(0.f, 0.f, 0.f, 0.f), v1 = v0;
        if (gm < NN) {
            v0 = *(const float4*)&g_h[(size_t)gm * DD + k8];
            v1 = *(const float4*)&g_h[(size_t)gm * DD + k8 + 4];
        }
        u64* d = sA + r * LKS + (k8 >> 3) * 4;
        d[0] = pack2u(to_tf32(v0.x), to_tf32(v1.x));
        d[1] = pack2u(to_tf32(v0.y), to_tf32(v1.y));
        d[2] = pack2u(to_tf32(v0.z), to_tf32(v1.z));
        d[3] = pack2u(to_tf32(v0.w), to_tf32(v1.w));
    }
    for (int idx = tid; idx < DD * (DD / 8); idx += 256) {
        int n = idx & 127, k0 = idx >> 7;
        float w[8];
#pragma unroll
        for (int j = 0; j < 8; j++) w[j] = W[(k0 * 8 + j) * DD + n];
#pragma unroll
        for (int j = 0; j < 4; j++)
            sW[n * LKS + k0 * 4 + j] = pack2u(to_tf32(w[j]), to_tf32(w[j + 4]));
    }
    __syncthreads();

    int lane = tid & 31, wm = tid >> 5;
    int gid = lane >> 2, q = lane & 3;
    int row_base = (wm & 3) * 16;
    int n_base = (wm >> 2) * 64;
    int r0 = row_base + gid, r1 = r0 + 8;
    const u64* ar0 = sA + r0 * LKS;
    const u64* ar1 = sA + r1 * LKS;

    float d[8][4];
#pragma unroll
    for (int n8 = 0; n8 < 8; n8++)
#pragma unroll
        for (int j = 0; j < 4; j++) d[n8][j] = 0.f;

#pragma unroll
    for (int k0 = 0; k0 < 16; k0++) {
        u64 pa0 = ar0[k0 * 4 + q];
        u64 pa1 = ar1[k0 * 4 + q];
        uint32_t a0 = (uint32_t)pa0, a2 = (uint32_t)(pa0 >> 32);
        uint32_t a1 = (uint32_t)pa1, a3 = (uint32_t)(pa1 >> 32);
#pragma unroll
        for (int n8 = 0; n8 < 8; n8++) {
            u64 pb = sW[(n_base + n8 * 8 + gid) * LKS + k0 * 4 + q];
            uint32_t b0 = (uint32_t)pb, b1 = (uint32_t)(pb >> 32);
            asm volatile(
                "mma.sync.aligned.m16n8k8.row.col.f32.tf32.tf32.f32 "
                "{%0,%1,%2,%3}, {%4,%5,%6,%7}, {%8,%9}, {%0,%1,%2,%3};"
                : "+f"(d[n8][0]), "+f"(d[n8][1]), "+f"(d[n8][2]), "+f"(d[n8][3])
                : "r"(a0), "r"(a1), "r"(a2), "r"(a3), "r"(b0), "r"(b1));
        }
    }

    int gm0 = m0 + r0, gm1 = m0 + r1;
#pragma unroll
    for (int n8 = 0; n8 < 8; n8++) {
        int c = n_base + n8 * 8 + 2 * q;
        float2 bb = *(const float2*)&bv[c];
        if (gm0 < NN) {
            float2 o = make_float2(d[n8][0] + bb.x, d[n8][1] + bb.y);
            *(float2*)&dst[(size_t)gm0 * DD + c] = o;
            dsth[(size_t)gm0 * 64 + (c >> 1)] = pack_bf2(o.x, o.y);
        }
        if (gm1 < NN) {
            float2 o = make_float2(d[n8][2] + bb.x, d[n8][3] + bb.y);
            *(float2*)&dst[(size_t)gm1 * DD + c] = o;
            dsth[(size_t)gm1 * 64 + (c >> 1)] = pack_bf2(o.x, o.y);
        }
    }
}

// ---------------- pass A: bf16 m16n8k16 TC ee GEMM + logits + exp ------------------
// 128 CSR-slot edges/block, 8 warps; 64 MMAs/warp (half the tf32 count), A hoisted.
#define PA_EDGES 128
#define EFSB 20   // u64 stride per row: 16 frags + 4 pad (same mod-32 bank residue as 36)
#define PASSA_SMEM (PA_EDGES * EFSB * 8 + DD * EFSB * 8 + DD * 4)
__global__ __launch_bounds__(256, 4) void passA_kernel(const float* __restrict__ We,
                                                       const float* __restrict__ att) {
    extern __shared__ char smem_raw[];
    u64*   sEf = (u64*)smem_raw;                            // [128 rows][EFSB]
    u64*   sWe = (u64*)(smem_raw + PA_EDGES * EFSB * 8);    // [128 n][EFSB]
    float* sAtt = (float*)(smem_raw + PA_EDGES * EFSB * 8 + DD * EFSB * 8);
    __shared__ int sSrc[PA_EDGES], sDst[PA_EDGES];
    int tid = threadIdx.x;
    int eb = blockIdx.x * PA_EDGES;

    if (tid < PA_EDGES) {
        sSrc[tid] = g_csr[eb + tid].y;
        sDst[tid] = g_csr_dst[eb + tid];
    }
    if (tid < DD) sAtt[tid] = att[tid];
    // stage We as bf16 m16n8k16 fragments: (n, g) -> 4 u64
    for (int idx = tid; idx < DD * (EH / 16); idx += 256) {   // 512
        int n = idx & 127, gk = idx >> 7;
        float w[16];
#pragma unroll
        for (int j = 0; j < 16; j++) w[j] = We[(gk * 16 + j) * DD + n];
#pragma unroll
        for (int q = 0; q < 4; q++)
            sWe[n * EFSB + gk * 4 + q] =
                pack2u(pack_bf2(w[2 * q], w[2 * q + 1]),
                       pack_bf2(w[2 * q + 8], w[2 * q + 9]));
    }
    // stage ef: pure linear uint4 copy (pre-formatted by edge_enc)
    for (int idx = tid; idx < PA_EDGES * 8; idx += 256) {     // 1024
        int r = idx >> 3, c2 = (idx & 7) << 1;
        uint4 v = *(const uint4*)&g_ef2[(size_t)(eb + r) * 16 + c2];
        *(uint4*)&sEf[r * EFSB + c2] = v;
    }
    __syncthreads();

    int lane = tid & 31, wm = tid >> 5;
    int gid = lane >> 2, q = lane & 3;

    int r0 = wm * 16 + gid;
    int r1 = r0 + 8;
    const uint32_t* xl0h = g_xlh + (size_t)sSrc[r0] * 64;
    const uint32_t* xr0h = g_xrh + (size_t)sDst[r0] * 64;
    const uint32_t* xl1h = g_xlh + (size_t)sSrc[r1] * 64;
    const uint32_t* xr1h = g_xrh + (size_t)sDst[r1] * 64;

    // hoist all A fragments: 8 LDS.64
    u64 A0[4], A1[4];
    {
        const u64* efr0 = sEf + r0 * EFSB;
        const u64* efr1 = sEf + r1 * EFSB;
#pragma unroll
        for (int gk = 0; gk < 4; gk++) {
            A0[gk] = efr0[gk * 4 + q];
            A1[gk] = efr1[gk * 4 + q];
        }
    }

    float h0[8], h1[8];
#pragma unroll
    for (int h = 0; h < 8; h++) { h0[h] = 0.f; h1[h] = 0.f; }

#pragma unroll
    for (int half = 0; half < 2; half++) {
        float d[8][4];
#pragma unroll
        for (int n8 = 0; n8 < 8; n8++)
#pragma unroll
            for (int j = 0; j < 4; j++) d[n8][j] = 0.f;

#pragma unroll
        for (int gk = 0; gk < 4; gk++) {
            uint32_t a0 = (uint32_t)A0[gk], a2 = (uint32_t)(A0[gk] >> 32);
            uint32_t a1 = (uint32_t)A1[gk], a3 = (uint32_t)(A1[gk] >> 32);
#pragma unroll
            for (int n8 = 0; n8 < 8; n8++) {
                int n = half * 8 + n8;
                u64 pb = sWe[(n * 8 + gid) * EFSB + gk * 4 + q];
                uint32_t b0 = (uint32_t)pb, b1 = (uint32_t)(pb >> 32);
                asm volatile(
                    "mma.sync.aligned.m16n8k16.row.col.f32.bf16.bf16.f32 "
                    "{%0,%1,%2,%3}, {%4,%5,%6,%7}, {%8,%9}, {%0,%1,%2,%3};"
                    : "+f"(d[n8][0]), "+f"(d[n8][1]), "+f"(d[n8][2]), "+f"(d[n8][3])
                    : "r"(a0), "r"(a1), "r"(a2), "r"(a3), "r"(b0), "r"(b1));
            }
        }
#pragma unroll
        for (int n8 = 0; n8 < 8; n8++) {
            int n = half * 8 + n8;
            int ci = n * 4 + q;
            float2 av = *(const float2*)&sAtt[n * 8 + q * 2];
            float2 l0v = unpack_bf2(xl0h[ci]);
            float2 r0v = unpack_bf2(xr0h[ci]);
            float2 l1v = unpack_bf2(xl1h[ci]);
            float2 r1v = unpack_bf2(xr1h[ci]);
            float v00 = d[n8][0] + l0v.x + r0v.x; v00 = v00 > 0.f ? v00 : 0.2f * v00;
            float v01 = d[n8][1] + l0v.y + r0v.y; v01 = v01 > 0.f ? v01 : 0.2f * v01;
            float v10 = d[n8][2] + l1v.x + r1v.x; v10 = v10 > 0.f ? v10 : 0.2f * v10;
            float v11 = d[n8][3] + l1v.y + r1v.y; v11 = v11 > 0.f ? v11 : 0.2f * v11;
            h0[n >> 1] += v00 * av.x + v01 * av.y;
            h1[n >> 1] += v10 * av.x + v11 * av.y;
        }
    }
#pragma unroll
    for (int h = 0; h < 8; h++) {
        h0[h] += __shfl_xor_sync(0xffffffffu, h0[h], 1);
        h0[h] += __shfl_xor_sync(0xffffffffu, h0[h], 2);
        h1[h] += __shfl_xor_sync(0xffffffffu, h1[h], 1);
        h1[h] += __shfl_xor_sync(0xffffffffu, h1[h], 2);
    }
    size_t p0 = (size_t)(eb + r0) * HH;
    size_t p1 = (size_t)(eb + r1) * HH;
    g_a[p0 + 2 * q]     = expf(h0[2 * q]);
    g_a[p0 + 2 * q + 1] = expf(h0[2 * q + 1]);
    g_a[p1 + 2 * q]     = expf(h1[2 * q]);
    g_a[p1 + 2 * q + 1] = expf(h1[2 * q + 1]);
}

// ---------------- pass B: per-dst gather (no atomics) + fused residual+LN+relu -----
__global__ void passB_kernel(const float* __restrict__ cb,
                             const float* __restrict__ g,
                             const float* __restrict__ beta) {
    int node = (blockIdx.x * blockDim.x + threadIdx.x) >> 5;
    int lane = threadIdx.x & 31;
    if (node >= NN) return;
    int start = g_rowptr[node], end = g_rowptr[node + 1];

    float s = 0.f;
    for (int p0 = start; p0 < end; p0 += 4) {
        int p = p0 + (lane >> 3);
        if (p < end) s += g_a[(size_t)p * HH + (lane & 7)];
    }
    s += __shfl_xor_sync(0xffffffffu, s, 8);
    s += __shfl_xor_sync(0xffffffffu, s, 16);
    float sh = __shfl_sync(0xffffffffu, s, lane >> 2);
    float rinv = 1.0f / (sh + 1e-16f);

    int head = lane >> 2;
    float4 acc = make_float4(0.f, 0.f, 0.f, 0.f);
    int p = start;
    for (; p + 4 <= end; p += 4) {
        int s0 = g_csr[p].y,     s1 = g_csr[p + 1].y;
        int s2 = g_csr[p + 2].y, s3 = g_csr[p + 3].y;
        float a0 = g_a[(size_t)(p)     * HH + head];
        float a1 = g_a[(size_t)(p + 1) * HH + head];
        float a2 = g_a[(size_t)(p + 2) * HH + head];
        float a3 = g_a[(size_t)(p + 3) * HH + head];
        float4 x0 = *(const float4*)&g_xl[(size_t)s0 * DD + 4 * lane];
        float4 x1 = *(const float4*)&g_xl[(size_t)s1 * DD + 4 * lane];
        float4 x2 = *(const float4*)&g_xl[(size_t)s2 * DD + 4 * lane];
        float4 x3 = *(const float4*)&g_xl[(size_t)s3 * DD + 4 * lane];
        acc.x += a0 * x0.x + a1 * x1.x + a2 * x2.x + a3 * x3.x;
        acc.y += a0 * x0.y + a1 * x1.y + a2 * x2.y + a3 * x3.y;
        acc.z += a0 * x0.z + a1 * x1.z + a2 * x2.z + a3 * x3.z;
        acc.w += a0 * x0.w + a1 * x1.w + a2 * x2.w + a3 * x3.w;
    }
    for (; p < end; p++) {
        int sn = g_csr[p].y;
        float al = g_a[(size_t)p * HH + head];
        float4 xv = *(const float4*)&g_xl[(size_t)sn * DD + 4 * lane];
        acc.x += al * xv.x; acc.y += al * xv.y;
        acc.z += al * xv.z; acc.w += al * xv.w;
    }
    acc.x *= rinv; acc.y *= rinv; acc.z *= rinv; acc.w *= rinv;

    int d0 = 4 * lane;
    float4 hv = *(const float4*)&g_h[node * DD + d0];
    float4 cv = *(const float4*)&cb[d0];
    float a0 = acc.x + cv.x + hv.x;
    float a1 = acc.y + cv.y + hv.y;
    float a2 = acc.z + cv.z + hv.z;
    float a3 = acc.w + cv.w + hv.w;
    float m = warp_sum(a0 + a1 + a2 + a3) * (1.0f / DD);
    float e0d = a0 - m, e1d = a1 - m, e2d = a2 - m, e3d = a3 - m;
    float v = warp_sum(e0d * e0d + e1d * e1d + e2d * e2d + e3d * e3d) * (1.0f / DD);
    float rstd = rsqrtf(v + 1e-5f);
    float4 gv = *(const float4*)&g[d0];
    float4 bv = *(const float4*)&beta[d0];
    float4 o;
    o.x = fmaxf(e0d * rstd * gv.x + bv.x, 0.f);
    o.y = fmaxf(e1d * rstd * gv.y + bv.y, 0.f);
    o.z = fmaxf(e2d * rstd * gv.z + bv.z, 0.f);
    o.w = fmaxf(e3d * rstd * gv.w + bv.w, 0.f);
    *(float4*)&g_h[node * DD + d0] = o;
}

// ---------------- head: relu(h@W1+b1) @ W2 -> sigmoid. 1 warp/node -----------------
__global__ void head_kernel(float* __restrict__ out,
                            const float* __restrict__ W1, const float* __restrict__ b1,
                            const float* __restrict__ W2, const float* __restrict__ b2) {
    int warp = (blockIdx.x * blockDim.x + threadIdx.x) >> 5;
    int lane = threadIdx.x & 31;
    if (warp >= NN) return;
    float hr[4];
#pragma unroll
    for (int q = 0; q < 4; q++) hr[q] = g_h[warp * DD + q * 32 + lane];
    float z0 = b1[lane], z1 = b1[lane + 32];
#pragma unroll
    for (int q = 0; q < 4; q++) {
#pragma unroll 8
        for (int kk = 0; kk < 32; kk++) {
            float hk = __shfl_sync(0xffffffffu, hr[q], kk);
            int k = q * 32 + kk;
            z0 += hk * W1[k * 64 + lane];
            z1 += hk * W1[k * 64 + 32 + lane];
        }
    }
    z0 = fmaxf(z0, 0.f);
    z1 = fmaxf(z1, 0.f);
    float p = z0 * W2[lane] + z1 * W2[lane + 32];
    p = warp_sum(p);
    if (lane == 0) out[warp] = 1.0f / (1.0f + expf(-(p + b2[0])));
}

// ---------------- launch ----------------------------------------------------------
extern "C" void kernel_launch(void* const* d_in, const int* in_sizes, int n_in,
                              void* d_out, int out_size) {
    const float* x    = (const float*)d_in[0];
    const int*   ei   = (const int*)  d_in[1];
    const float* ea   = (const float*)d_in[2];
    const float* neW  = (const float*)d_in[3];
    const float* neb  = (const float*)d_in[4];
    const float* neg  = (const float*)d_in[5];
    const float* nebt = (const float*)d_in[6];
    const float* eeW  = (const float*)d_in[7];
    const float* eeb  = (const float*)d_in[8];
    const float* eeg  = (const float*)d_in[9];
    const float* eebt = (const float*)d_in[10];
    const float* Wl   = (const float*)d_in[11];
    const float* bl   = (const float*)d_in[12];
    const float* Wr   = (const float*)d_in[13];
    const float* br   = (const float*)d_in[14];
    const float* We   = (const float*)d_in[15];
    const float* att  = (const float*)d_in[16];
    const float* cb   = (const float*)d_in[17];
    const float* lng  = (const float*)d_in[18];
    const float* lnb  = (const float*)d_in[19];
    const float* W1   = (const float*)d_in[20];
    const float* b1   = (const float*)d_in[21];
    const float* W2   = (const float*)d_in[22];
    const float* b2   = (const float*)d_in[23];
    float* out = (float*)d_out;

    cudaFuncSetAttribute(lin_kernel, cudaFuncAttributeMaxDynamicSharedMemorySize,
                         LIN_SMEM);
    cudaFuncSetAttribute(passA_kernel, cudaFuncAttributeMaxDynamicSharedMemorySize,
                         PASSA_SMEM);

    dim3 lin_grid((NN + LIN_ROWS - 1) / LIN_ROWS, 2);
    int passa_grid = EE / PA_EDGES;

    node_enc_kernel<<<NN / 8, 256>>>(x, neW, neb, neg, nebt);                    // 0
    csr_zero_kernel<<<(NN + 255) / 256, 256>>>();                                // 1
    csr_count_kernel<<<(EE + 255) / 256, 256>>>(ei);                             // 2
    lin_kernel<<<lin_grid, 256, LIN_SMEM>>>(Wl, bl, Wr, br);                     // 3 (profiled; control)
    csr_scan_kernel<<<1, 1024>>>();                                              // 4
    csr_scatter_kernel<<<(EE + 255) / 256, 256>>>(ei);                           // 5
    edge_enc_kernel<<<EE / 8, 256>>>(ea, eeW, eeb, eeg, eebt);                   // 6 (needs g_slot)

    for (int l = 0; l < LL; l++) {
        if (l > 0)
            lin_kernel<<<lin_grid, 256, LIN_SMEM>>>(Wl + l * DD * DD, bl + l * DD,
                                                    Wr + l * DD * DD, br + l * DD);
        passA_kernel<<<passa_grid, 256, PASSA_SMEM>>>(We + l * EH * DD,
                                                      att + l * HH * CC);
        passB_kernel<<<(NN * 32 + 255) / 256, 256>>>(cb + l * DD, lng + l * DD,
                                                     lnb + l * DD);
    }
    head_kernel<<<NN / 8, 256>>>(out, W1, b1, W2, b2);
}

// round 14
// speedup vs baseline: 1.3165x; 1.0793x over previous
#include <cuda_runtime.h>
#include <math.h>
#include <stdint.h>

#define NN 50000
#define EE 400000
#define DD 128
#define HH 8
#define CC 16
#define EH 64
#define LL 6

static_assert(EE % 128 == 0, "edge tiling");
static_assert(NN % 8 == 0, "node tiling");

typedef unsigned long long u64;

// ---------------- device scratch (static; no allocations allowed) ----------------
__device__ __align__(16) float g_h  [NN * DD];   // node features
__device__ __align__(16) float g_xl [NN * DD];   // lin_l output (fp32)
__device__ __align__(16) float g_xr [NN * DD];   // lin_r output (fp32)
__device__ __align__(8) uint32_t g_xlh[NN * 64]; // bf16x2 mirror of xl (for passA)
__device__ __align__(8) uint32_t g_xrh[NN * 64]; // bf16x2 mirror of xr (for passA)
__device__ __align__(16) u64 g_ef2[EE * 16];     // ef, CSR-slot order, bf16 m16n8k16 frags
__device__             float g_a   [EE * HH];    // exp(logit), indexed by CSR SLOT
// CSR by destination node (built once per launch)
__device__ int  g_cnt   [NN];
__device__ int  g_wptr  [NN];
__device__ int  g_rowptr[NN + 1];
__device__ int2 g_csr    [EE];   // (orig edge id, src node) per slot
__device__ int  g_csr_dst[EE];   // dst node per slot
__device__ int  g_slot   [EE];   // edge id -> CSR slot (inverse map)

__device__ __forceinline__ float warp_sum(float v) {
#pragma unroll
    for (int o = 16; o; o >>= 1) v += __shfl_xor_sync(0xffffffffu, v, o);
    return v;
}
__device__ __forceinline__ u64 pack2u(uint32_t lo, uint32_t hi) {
    return ((u64)hi << 32) | (u64)lo;
}
__device__ __forceinline__ uint32_t pack_bf2(float lo, float hi) {
    uint32_t r;
    asm("cvt.rn.bf16x2.f32 %0, %1, %2;" : "=r"(r) : "f"(hi), "f"(lo));
    return r;
}
__device__ __forceinline__ float2 unpack_bf2(uint32_t u) {
    float2 r;
    r.x = __uint_as_float(u << 16);
    r.y = __uint_as_float(u & 0xffff0000u);
    return r;
}

// ---------------- node encoder: x(N,9) -> LN -> relu -> g_h(N,128). 1 warp/node ----
__global__ void node_enc_kernel(const float* __restrict__ x,
                                const float* __restrict__ W,
                                const float* __restrict__ b,
                                const float* __restrict__ g,
                                const float* __restrict__ beta) {
    int warp = (blockIdx.x * blockDim.x + threadIdx.x) >> 5;
    int lane = threadIdx.x & 31;
    if (warp >= NN) return;
    float acc[4];
#pragma unroll
    for (int j = 0; j < 4; j++) acc[j] = b[lane + 32 * j];
#pragma unroll
    for (int k = 0; k < 9; k++) {
        float xv = x[warp * 9 + k];
#pragma unroll
        for (int j = 0; j < 4; j++) acc[j] += xv * W[k * DD + lane + 32 * j];
    }
    float s = 0.f;
#pragma unroll
    for (int j = 0; j < 4; j++) s += acc[j];
    float m = warp_sum(s) * (1.0f / DD);
    float v = 0.f;
#pragma unroll
    for (int j = 0; j < 4; j++) { float d = acc[j] - m; v += d * d; }
    v = warp_sum(v) * (1.0f / DD);
    float rstd = rsqrtf(v + 1e-5f);
#pragma unroll
    for (int j = 0; j < 4; j++) {
        int d = lane + 32 * j;
        float y = (acc[j] - m) * rstd * g[d] + beta[d];
        g_h[warp * DD + d] = fmaxf(y, 0.0f);
    }
}

// ---------------- edge encoder -> g_ef2[slot], bf16 m16n8k16 fragment layout -------
__global__ void edge_enc_kernel(const float* __restrict__ ea,
                                const float* __restrict__ W,
                                const float* __restrict__ b,
                                const float* __restrict__ g,
                                const float* __restrict__ beta) {
    int warp = (blockIdx.x * blockDim.x + threadIdx.x) >> 5;
    int lane = threadIdx.x & 31;
    if (warp >= EE) return;
    float a0 = b[lane], a1 = b[lane + 32];
#pragma unroll
    for (int k = 0; k < 3; k++) {
        float xv = ea[warp * 3 + k];
        a0 += xv * W[k * EH + lane];
        a1 += xv * W[k * EH + 32 + lane];
    }
    float m = warp_sum(a0 + a1) * (1.0f / EH);
    float d0v = a0 - m, d1v = a1 - m;
    float v = warp_sum(d0v * d0v + d1v * d1v) * (1.0f / EH);
    float rstd = rsqrtf(v + 1e-5f);
    float y0 = fmaxf(d0v * rstd * g[lane] + beta[lane], 0.f);           // dim = lane
    float y1 = fmaxf(d1v * rstd * g[lane + 32] + beta[lane + 32], 0.f); // dim = lane+32

    int L = lane & 15;
    int gk = L >> 2, q = L & 3;
    int d0 = gk * 16 + 2 * q;
    int d1 = d0 + 1, d2 = d0 + 8, d3 = d0 + 9;
    float s0a = __shfl_sync(0xffffffffu, y0, d0 & 31);
    float s0b = __shfl_sync(0xffffffffu, y1, d0 & 31);
    float s1a = __shfl_sync(0xffffffffu, y0, d1 & 31);
    float s1b = __shfl_sync(0xffffffffu, y1, d1 & 31);
    float s2a = __shfl_sync(0xffffffffu, y0, d2 & 31);
    float s2b = __shfl_sync(0xffffffffu, y1, d2 & 31);
    float s3a = __shfl_sync(0xffffffffu, y0, d3 & 31);
    float s3b = __shfl_sync(0xffffffffu, y1, d3 & 31);
    if (lane < 16) {
        float v0 = (d0 < 32) ? s0a : s0b;
        float v1 = (d1 < 32) ? s1a : s1b;
        float v2 = (d2 < 32) ? s2a : s2b;
        float v3 = (d3 < 32) ? s3a : s3b;
        int slot = g_slot[warp];
        g_ef2[(size_t)slot * 16 + L] =
            pack2u(pack_bf2(v0, v1), pack_bf2(v2, v3));
    }
}

// ---------------- CSR build (once per launch) --------------------------------------
__global__ void csr_zero_kernel() {
    int i = blockIdx.x * blockDim.x + threadIdx.x;
    if (i < NN) g_cnt[i] = 0;
}
__global__ void csr_count_kernel(const int* __restrict__ ei) {
    int e = blockIdx.x * blockDim.x + threadIdx.x;
    if (e < EE) atomicAdd(&g_cnt[ei[EE + e]], 1);
}
__global__ void csr_scan_kernel() {
    __shared__ int warpsum[32];
    __shared__ int s_total;
    int tid = threadIdx.x, lane = tid & 31, wid = tid >> 5;
    if (tid == 0) { s_total = 0; g_rowptr[0] = 0; }
    __syncthreads();
    for (int base = 0; base < NN; base += 1024) {
        int i = base + tid;
        int v = (i < NN) ? g_cnt[i] : 0;
        int x = v;
#pragma unroll
        for (int o = 1; o < 32; o <<= 1) {
            int t = __shfl_up_sync(0xffffffffu, x, o);
            if (lane >= o) x += t;
        }
        if (lane == 31) warpsum[wid] = x;
        __syncthreads();
        if (wid == 0) {
            int w = warpsum[lane];
#pragma unroll
            for (int o = 1; o < 32; o <<= 1) {
                int t = __shfl_up_sync(0xffffffffu, w, o);
                if (lane >= o) w += t;
            }
            warpsum[lane] = w;
        }
        __syncthreads();
        int incl = s_total + (wid ? warpsum[wid - 1] : 0) + x;
        if (i < NN) {
            g_rowptr[i + 1] = incl;
            g_wptr[i] = incl - v;
        }
        __syncthreads();
        if (tid == 0) s_total += warpsum[31];
        __syncthreads();
    }
}
__global__ void csr_scatter_kernel(const int* __restrict__ ei) {
    int e = blockIdx.x * blockDim.x + threadIdx.x;
    if (e < EE) {
        int d = ei[EE + e];
        int pos = atomicAdd(&g_wptr[d], 1);
        g_csr[pos] = make_int2(e, ei[e]);
        g_csr_dst[pos] = d;
        g_slot[e] = pos;
    }
}

// ---------------- xl/xr GEMM: bf16 m16n8k16 tensor cores, 64 rows/block, K=128 -----
#define LIN_ROWS 64
#define LKSB 36   // u64 stride per row: 32 frags (8 k-groups x 4) + 4 pad
#define LIN_SMEM ((LIN_ROWS + DD) * LKSB * 8)
__global__ __launch_bounds__(256, 3) void lin_kernel(
    const float* __restrict__ Wl, const float* __restrict__ bl,
    const float* __restrict__ Wr, const float* __restrict__ br) {
    extern __shared__ char smem_raw[];
    u64* sA = (u64*)smem_raw;                          // [64 rows][LKSB]
    u64* sW = (u64*)(smem_raw + LIN_ROWS * LKSB * 8);  // [128 n][LKSB]
    const float* W  = blockIdx.y ? Wr : Wl;
    const float* bv = blockIdx.y ? br : bl;
    float* dst = blockIdx.y ? g_xr : g_xl;
    uint32_t* dsth = blockIdx.y ? g_xrh : g_xlh;
    int m0 = blockIdx.x * LIN_ROWS;
    int tid = threadIdx.x;

    // stage A (h rows) as bf16 frags: 64 rows x 8 k-groups
    for (int idx = tid; idx < LIN_ROWS * (DD / 16); idx += 256) {  // 512
        int r = idx >> 3, gk = idx & 7;
        int gm = m0 + r;
        float4 v0 = make_float4(0.f, 0.f, 0.f, 0.f), v1 = v0, v2 = v0, v3 = v0;
        if (gm < NN) {
            const float* hp = &g_h[(size_t)gm * DD + gk * 16];
            v0 = *(const float4*)&hp[0];
            v1 = *(const float4*)&hp[4];
            v2 = *(const float4*)&hp[8];
            v3 = *(const float4*)&hp[12];
        }
        u64* d = sA + r * LKSB + gk * 4;
        d[0] = pack2u(pack_bf2(v0.x, v0.y), pack_bf2(v2.x, v2.y));
        d[1] = pack2u(pack_bf2(v0.z, v0.w), pack_bf2(v2.z, v2.w));
        d[2] = pack2u(pack_bf2(v1.x, v1.y), pack_bf2(v3.x, v3.y));
        d[3] = pack2u(pack_bf2(v1.z, v1.w), pack_bf2(v3.z, v3.w));
    }
    // stage W as bf16 frags: 128 n x 8 k-groups (column gather)
    for (int idx = tid; idx < DD * (DD / 16); idx += 256) {        // 1024
        int n = idx & 127, gk = idx >> 7;
        float w[16];
#pragma unroll
        for (int j = 0; j < 16; j++) w[j] = W[(gk * 16 + j) * DD + n];
#pragma unroll
        for (int q = 0; q < 4; q++)
            sW[n * LKSB + gk * 4 + q] =
                pack2u(pack_bf2(w[2 * q], w[2 * q + 1]),
                       pack_bf2(w[2 * q + 8], w[2 * q + 9]));
    }
    __syncthreads();

    int lane = tid & 31, wm = tid >> 5;
    int gid = lane >> 2, q = lane & 3;
    int row_base = (wm & 3) * 16;
    int n_base = (wm >> 2) * 64;
    int r0 = row_base + gid, r1 = r0 + 8;
    const u64* ar0 = sA + r0 * LKSB;
    const u64* ar1 = sA + r1 * LKSB;

    float d[8][4];
#pragma unroll
    for (int n8 = 0; n8 < 8; n8++)
#pragma unroll
        for (int j = 0; j < 4; j++) d[n8][j] = 0.f;

#pragma unroll
    for (int gk = 0; gk < 8; gk++) {
        u64 pa0 = ar0[gk * 4 + q];
        u64 pa1 = ar1[gk * 4 + q];
        uint32_t a0 = (uint32_t)pa0, a2 = (uint32_t)(pa0 >> 32);
        uint32_t a1 = (uint32_t)pa1, a3 = (uint32_t)(pa1 >> 32);
#pragma unroll
        for (int n8 = 0; n8 < 8; n8++) {
            u64 pb = sW[(n_base + n8 * 8 + gid) * LKSB + gk * 4 + q];
            uint32_t b0 = (uint32_t)pb, b1 = (uint32_t)(pb >> 32);
            asm volatile(
                "mma.sync.aligned.m16n8k16.row.col.f32.bf16.bf16.f32 "
                "{%0,%1,%2,%3}, {%4,%5,%6,%7}, {%8,%9}, {%0,%1,%2,%3};"
                : "+f"(d[n8][0]), "+f"(d[n8][1]), "+f"(d[n8][2]), "+f"(d[n8][3])
                : "r"(a0), "r"(a1), "r"(a2), "r"(a3), "r"(b0), "r"(b1));
        }
    }

    int gm0 = m0 + r0, gm1 = m0 + r1;
#pragma unroll
    for (int n8 = 0; n8 < 8; n8++) {
        int c = n_base + n8 * 8 + 2 * q;
        float2 bb = *(const float2*)&bv[c];
        if (gm0 < NN) {
            float2 o = make_float2(d[n8][0] + bb.x, d[n8][1] + bb.y);
            *(float2*)&dst[(size_t)gm0 * DD + c] = o;
            dsth[(size_t)gm0 * 64 + (c >> 1)] = pack_bf2(o.x, o.y);
        }
        if (gm1 < NN) {
            float2 o = make_float2(d[n8][2] + bb.x, d[n8][3] + bb.y);
            *(float2*)&dst[(size_t)gm1 * DD + c] = o;
            dsth[(size_t)gm1 * 64 + (c >> 1)] = pack_bf2(o.x, o.y);
        }
    }
}

// ---------------- pass A: bf16 m16n8k16 TC ee GEMM + logits + exp ------------------
#define PA_EDGES 128
#define EFSB 20   // u64 stride per row: 16 frags + 4 pad
#define PASSA_SMEM (PA_EDGES * EFSB * 8 + DD * EFSB * 8 + DD * 4)
__global__ __launch_bounds__(256, 4) void passA_kernel(const float* __restrict__ We,
                                                       const float* __restrict__ att) {
    extern __shared__ char smem_raw[];
    u64*   sEf = (u64*)smem_raw;                            // [128 rows][EFSB]
    u64*   sWe = (u64*)(smem_raw + PA_EDGES * EFSB * 8);    // [128 n][EFSB]
    float* sAtt = (float*)(smem_raw + PA_EDGES * EFSB * 8 + DD * EFSB * 8);
    __shared__ int sSrc[PA_EDGES], sDst[PA_EDGES];
    int tid = threadIdx.x;
    int eb = blockIdx.x * PA_EDGES;

    if (tid < PA_EDGES) {
        sSrc[tid] = g_csr[eb + tid].y;
        sDst[tid] = g_csr_dst[eb + tid];
    }
    if (tid < DD) sAtt[tid] = att[tid];
    for (int idx = tid; idx < DD * (EH / 16); idx += 256) {
        int n = idx & 127, gk = idx >> 7;
        float w[16];
#pragma unroll
        for (int j = 0; j < 16; j++) w[j] = We[(gk * 16 + j) * DD + n];
#pragma unroll
        for (int q = 0; q < 4; q++)
            sWe[n * EFSB + gk * 4 + q] =
                pack2u(pack_bf2(w[2 * q], w[2 * q + 1]),
                       pack_bf2(w[2 * q + 8], w[2 * q + 9]));
    }
    for (int idx = tid; idx < PA_EDGES * 8; idx += 256) {
        int r = idx >> 3, c2 = (idx & 7) << 1;
        uint4 v = *(const uint4*)&g_ef2[(size_t)(eb + r) * 16 + c2];
        *(uint4*)&sEf[r * EFSB + c2] = v;
    }
    __syncthreads();

    int lane = tid & 31, wm = tid >> 5;
    int gid = lane >> 2, q = lane & 3;

    int r0 = wm * 16 + gid;
    int r1 = r0 + 8;
    const uint32_t* xl0h = g_xlh + (size_t)sSrc[r0] * 64;
    const uint32_t* xr0h = g_xrh + (size_t)sDst[r0] * 64;
    const uint32_t* xl1h = g_xlh + (size_t)sSrc[r1] * 64;
    const uint32_t* xr1h = g_xrh + (size_t)sDst[r1] * 64;

    u64 A0[4], A1[4];
    {
        const u64* efr0 = sEf + r0 * EFSB;
        const u64* efr1 = sEf + r1 * EFSB;
#pragma unroll
        for (int gk = 0; gk < 4; gk++) {
            A0[gk] = efr0[gk * 4 + q];
            A1[gk] = efr1[gk * 4 + q];
        }
    }

    float h0[8], h1[8];
#pragma unroll
    for (int h = 0; h < 8; h++) { h0[h] = 0.f; h1[h] = 0.f; }

#pragma unroll
    for (int half = 0; half < 2; half++) {
        float d[8][4];
#pragma unroll
        for (int n8 = 0; n8 < 8; n8++)
#pragma unroll
            for (int j = 0; j < 4; j++) d[n8][j] = 0.f;

#pragma unroll
        for (int gk = 0; gk < 4; gk++) {
            uint32_t a0 = (uint32_t)A0[gk], a2 = (uint32_t)(A0[gk] >> 32);
            uint32_t a1 = (uint32_t)A1[gk], a3 = (uint32_t)(A1[gk] >> 32);
#pragma unroll
            for (int n8 = 0; n8 < 8; n8++) {
                int n = half * 8 + n8;
                u64 pb = sWe[(n * 8 + gid) * EFSB + gk * 4 + q];
                uint32_t b0 = (uint32_t)pb, b1 = (uint32_t)(pb >> 32);
                asm volatile(
                    "mma.sync.aligned.m16n8k16.row.col.f32.bf16.bf16.f32 "
                    "{%0,%1,%2,%3}, {%4,%5,%6,%7}, {%8,%9}, {%0,%1,%2,%3};"
                    : "+f"(d[n8][0]), "+f"(d[n8][1]), "+f"(d[n8][2]), "+f"(d[n8][3])
                    : "r"(a0), "r"(a1), "r"(a2), "r"(a3), "r"(b0), "r"(b1));
            }
        }
#pragma unroll
        for (int n8 = 0; n8 < 8; n8++) {
            int n = half * 8 + n8;
            int ci = n * 4 + q;
            float2 av = *(const float2*)&sAtt[n * 8 + q * 2];
            float2 l0v = unpack_bf2(xl0h[ci]);
            float2 r0v = unpack_bf2(xr0h[ci]);
            float2 l1v = unpack_bf2(xl1h[ci]);
            float2 r1v = unpack_bf2(xr1h[ci]);
            float v00 = d[n8][0] + l0v.x + r0v.x; v00 = v00 > 0.f ? v00 : 0.2f * v00;
            float v01 = d[n8][1] + l0v.y + r0v.y; v01 = v01 > 0.f ? v01 : 0.2f * v01;
            float v10 = d[n8][2] + l1v.x + r1v.x; v10 = v10 > 0.f ? v10 : 0.2f * v10;
            float v11 = d[n8][3] + l1v.y + r1v.y; v11 = v11 > 0.f ? v11 : 0.2f * v11;
            h0[n >> 1] += v00 * av.x + v01 * av.y;
            h1[n >> 1] += v10 * av.x + v11 * av.y;
        }
    }
#pragma unroll
    for (int h = 0; h < 8; h++) {
        h0[h] += __shfl_xor_sync(0xffffffffu, h0[h], 1);
        h0[h] += __shfl_xor_sync(0xffffffffu, h0[h], 2);
        h1[h] += __shfl_xor_sync(0xffffffffu, h1[h], 1);
        h1[h] += __shfl_xor_sync(0xffffffffu, h1[h], 2);
    }
    size_t p0 = (size_t)(eb + r0) * HH;
    size_t p1 = (size_t)(eb + r1) * HH;
    g_a[p0 + 2 * q]     = expf(h0[2 * q]);
    g_a[p0 + 2 * q + 1] = expf(h0[2 * q + 1]);
    g_a[p1 + 2 * q]     = expf(h1[2 * q]);
    g_a[p1 + 2 * q + 1] = expf(h1[2 * q + 1]);
}

// ---------------- pass B: per-dst gather (no atomics) + fused residual+LN+relu -----
__global__ void passB_kernel(const float* __restrict__ cb,
                             const float* __restrict__ g,
                             const float* __restrict__ beta) {
    int node = (blockIdx.x * blockDim.x + threadIdx.x) >> 5;
    int lane = threadIdx.x & 31;
    if (node >= NN) return;
    int start = g_rowptr[node], end = g_rowptr[node + 1];

    float s = 0.f;
    for (int p0 = start; p0 < end; p0 += 4) {
        int p = p0 + (lane >> 3);
        if (p < end) s += g_a[(size_t)p * HH + (lane & 7)];
    }
    s += __shfl_xor_sync(0xffffffffu, s, 8);
    s += __shfl_xor_sync(0xffffffffu, s, 16);
    float sh = __shfl_sync(0xffffffffu, s, lane >> 2);
    float rinv = 1.0f / (sh + 1e-16f);

    int head = lane >> 2;
    float4 acc = make_float4(0.f, 0.f, 0.f, 0.f);
    int p = start;
    for (; p + 4 <= end; p += 4) {
        int s0 = g_csr[p].y,     s1 = g_csr[p + 1].y;
        int s2 = g_csr[p + 2].y, s3 = g_csr[p + 3].y;
        float a0 = g_a[(size_t)(p)     * HH + head];
        float a1 = g_a[(size_t)(p + 1) * HH + head];
        float a2 = g_a[(size_t)(p + 2) * HH + head];
        float a3 = g_a[(size_t)(p + 3) * HH + head];
        float4 x0 = *(const float4*)&g_xl[(size_t)s0 * DD + 4 * lane];
        float4 x1 = *(const float4*)&g_xl[(size_t)s1 * DD + 4 * lane];
        float4 x2 = *(const float4*)&g_xl[(size_t)s2 * DD + 4 * lane];
        float4 x3 = *(const float4*)&g_xl[(size_t)s3 * DD + 4 * lane];
        acc.x += a0 * x0.x + a1 * x1.x + a2 * x2.x + a3 * x3.x;
        acc.y += a0 * x0.y + a1 * x1.y + a2 * x2.y + a3 * x3.y;
        acc.z += a0 * x0.z + a1 * x1.z + a2 * x2.z + a3 * x3.z;
        acc.w += a0 * x0.w + a1 * x1.w + a2 * x2.w + a3 * x3.w;
    }
    for (; p < end; p++) {
        int sn = g_csr[p].y;
        float al = g_a[(size_t)p * HH + head];
        float4 xv = *(const float4*)&g_xl[(size_t)sn * DD + 4 * lane];
        acc.x += al * xv.x; acc.y += al * xv.y;
        acc.z += al * xv.z; acc.w += al * xv.w;
    }
    acc.x *= rinv; acc.y *= rinv; acc.z *= rinv; acc.w *= rinv;

    int d0 = 4 * lane;
    float4 hv = *(const float4*)&g_h[node * DD + d0];
    float4 cv = *(const float4*)&cb[d0];
    float a0 = acc.x + cv.x + hv.x;
    float a1 = acc.y + cv.y + hv.y;
    float a2 = acc.z + cv.z + hv.z;
    float a3 = acc.w + cv.w + hv.w;
    float m = warp_sum(a0 + a1 + a2 + a3) * (1.0f / DD);
    float e0d = a0 - m, e1d = a1 - m, e2d = a2 - m, e3d = a3 - m;
    float v = warp_sum(e0d * e0d + e1d * e1d + e2d * e2d + e3d * e3d) * (1.0f / DD);
    float rstd = rsqrtf(v + 1e-5f);
    float4 gv = *(const float4*)&g[d0];
    float4 bv = *(const float4*)&beta[d0];
    float4 o;
    o.x = fmaxf(e0d * rstd * gv.x + bv.x, 0.f);
    o.y = fmaxf(e1d * rstd * gv.y + bv.y, 0.f);
    o.z = fmaxf(e2d * rstd * gv.z + bv.z, 0.f);
    o.w = fmaxf(e3d * rstd * gv.w + bv.w, 0.f);
    *(float4*)&g_h[node * DD + d0] = o;
}

// ---------------- head: relu(h@W1+b1) @ W2 -> sigmoid. 1 warp/node -----------------
__global__ void head_kernel(float* __restrict__ out,
                            const float* __restrict__ W1, const float* __restrict__ b1,
                            const float* __restrict__ W2, const float* __restrict__ b2) {
    int warp = (blockIdx.x * blockDim.x + threadIdx.x) >> 5;
    int lane = threadIdx.x & 31;
    if (warp >= NN) return;
    float hr[4];
#pragma unroll
    for (int q = 0; q < 4; q++) hr[q] = g_h[warp * DD + q * 32 + lane];
    float z0 = b1[lane], z1 = b1[lane + 32];
#pragma unroll
    for (int q = 0; q < 4; q++) {
#pragma unroll 8
        for (int kk = 0; kk < 32; kk++) {
            float hk = __shfl_sync(0xffffffffu, hr[q], kk);
            int k = q * 32 + kk;
            z0 += hk * W1[k * 64 + lane];
            z1 += hk * W1[k * 64 + 32 + lane];
        }
    }
    z0 = fmaxf(z0, 0.f);
    z1 = fmaxf(z1, 0.f);
    float p = z0 * W2[lane] + z1 * W2[lane + 32];
    p = warp_sum(p);
    if (lane == 0) out[warp] = 1.0f / (1.0f + expf(-(p + b2[0])));
}

// ---------------- launch ----------------------------------------------------------
extern "C" void kernel_launch(void* const* d_in, const int* in_sizes, int n_in,
                              void* d_out, int out_size) {
    const float* x    = (const float*)d_in[0];
    const int*   ei   = (const int*)  d_in[1];
    const float* ea   = (const float*)d_in[2];
    const float* neW  = (const float*)d_in[3];
    const float* neb  = (const float*)d_in[4];
    const float* neg  = (const float*)d_in[5];
    const float* nebt = (const float*)d_in[6];
    const float* eeW  = (const float*)d_in[7];
    const float* eeb  = (const float*)d_in[8];
    const float* eeg  = (const float*)d_in[9];
    const float* eebt = (const float*)d_in[10];
    const float* Wl   = (const float*)d_in[11];
    const float* bl   = (const float*)d_in[12];
    const float* Wr   = (const float*)d_in[13];
    const float* br   = (const float*)d_in[14];
    const float* We   = (const float*)d_in[15];
    const float* att  = (const float*)d_in[16];
    const float* cb   = (const float*)d_in[17];
    const float* lng  = (const float*)d_in[18];
    const float* lnb  = (const float*)d_in[19];
    const float* W1   = (const float*)d_in[20];
    const float* b1   = (const float*)d_in[21];
    const float* W2   = (const float*)d_in[22];
    const float* b2   = (const float*)d_in[23];
    float* out = (float*)d_out;

    cudaFuncSetAttribute(lin_kernel, cudaFuncAttributeMaxDynamicSharedMemorySize,
                         LIN_SMEM);
    cudaFuncSetAttribute(passA_kernel, cudaFuncAttributeMaxDynamicSharedMemorySize,
                         PASSA_SMEM);

    dim3 lin_grid((NN + LIN_ROWS - 1) / LIN_ROWS, 2);
    int passa_grid = EE / PA_EDGES;

    node_enc_kernel<<<NN / 8, 256>>>(x, neW, neb, neg, nebt);                    // 0
    csr_zero_kernel<<<(NN + 255) / 256, 256>>>();                                // 1
    csr_count_kernel<<<(EE + 255) / 256, 256>>>(ei);                             // 2
    lin_kernel<<<lin_grid, 256, LIN_SMEM>>>(Wl, bl, Wr, br);                     // 3 (profiled)
    csr_scan_kernel<<<1, 1024>>>();                                              // 4
    csr_scatter_kernel<<<(EE + 255) / 256, 256>>>(ei);                           // 5
    edge_enc_kernel<<<EE / 8, 256>>>(ea, eeW, eeb, eeg, eebt);                   // 6 (needs g_slot)

    for (int l = 0; l < LL; l++) {
        if (l > 0)
            lin_kernel<<<lin_grid, 256, LIN_SMEM>>>(Wl + l * DD * DD, bl + l * DD,
                                                    Wr + l * DD * DD, br + l * DD);
        passA_kernel<<<passa_grid, 256, PASSA_SMEM>>>(We + l * EH * DD,
                                                      att + l * HH * CC);
        passB_kernel<<<(NN * 32 + 255) / 256, 256>>>(cb + l * DD, lng + l * DD,
                                                     lnb + l * DD);
    }
    head_kernel<<<NN / 8, 256>>>(out, W1, b1, W2, b2);
}

// round 15
// speedup vs baseline: 1.3583x; 1.0317x over previous
#include <cuda_runtime.h>
#include <math.h>
#include <stdint.h>

#define NN 50000
#define EE 400000
#define DD 128
#define HH 8
#define CC 16
#define EH 64
#define LL 6

static_assert(EE % 128 == 0, "edge tiling");
static_assert(NN % 8 == 0, "node tiling");

typedef unsigned long long u64;

// ---------------- device scratch (static; no allocations allowed) ----------------
__device__ __align__(16) float g_h  [NN * DD];   // node features
__device__ __align__(16) float g_xl [NN * DD];   // lin_l output (fp32)
__device__ __align__(16) float g_xr [NN * DD];   // lin_r output (fp32)
__device__ __align__(8) uint32_t g_xlh[NN * 64]; // bf16x2 mirror of xl
__device__ __align__(8) uint32_t g_xrh[NN * 64]; // bf16x2 mirror of xr
__device__ __align__(16) u64 g_ef2[EE * 16];     // ef, CSR-slot order, bf16 m16n8k16 frags
__device__             float g_a   [EE * HH];    // exp(logit), indexed by CSR SLOT
// CSR by destination node (built once per launch)
__device__ int  g_cnt   [NN];
__device__ int  g_wptr  [NN];
__device__ int  g_rowptr[NN + 1];
__device__ int2 g_csr    [EE];   // (orig edge id, src node) per slot
__device__ int  g_csr_dst[EE];   // dst node per slot
__device__ int  g_slot   [EE];   // edge id -> CSR slot (inverse map)

__device__ __forceinline__ float warp_sum(float v) {
#pragma unroll
    for (int o = 16; o; o >>= 1) v += __shfl_xor_sync(0xffffffffu, v, o);
    return v;
}
__device__ __forceinline__ u64 pack2u(uint32_t lo, uint32_t hi) {
    return ((u64)hi << 32) | (u64)lo;
}
__device__ __forceinline__ uint32_t pack_bf2(float lo, float hi) {
    uint32_t r;
    asm("cvt.rn.bf16x2.f32 %0, %1, %2;" : "=r"(r) : "f"(hi), "f"(lo));
    return r;
}
__device__ __forceinline__ float2 unpack_bf2(uint32_t u) {
    float2 r;
    r.x = __uint_as_float(u << 16);
    r.y = __uint_as_float(u & 0xffff0000u);
    return r;
}

// ---------------- node encoder: x(N,9) -> LN -> relu -> g_h(N,128). 1 warp/node ----
__global__ void node_enc_kernel(const float* __restrict__ x,
                                const float* __restrict__ W,
                                const float* __restrict__ b,
                                const float* __restrict__ g,
                                const float* __restrict__ beta) {
    int warp = (blockIdx.x * blockDim.x + threadIdx.x) >> 5;
    int lane = threadIdx.x & 31;
    if (warp >= NN) return;
    float acc[4];
#pragma unroll
    for (int j = 0; j < 4; j++) acc[j] = b[lane + 32 * j];
#pragma unroll
    for (int k = 0; k < 9; k++) {
        float xv = x[warp * 9 + k];
#pragma unroll
        for (int j = 0; j < 4; j++) acc[j] += xv * W[k * DD + lane + 32 * j];
    }
    float s = 0.f;
#pragma unroll
    for (int j = 0; j < 4; j++) s += acc[j];
    float m = warp_sum(s) * (1.0f / DD);
    float v = 0.f;
#pragma unroll
    for (int j = 0; j < 4; j++) { float d = acc[j] - m; v += d * d; }
    v = warp_sum(v) * (1.0f / DD);
    float rstd = rsqrtf(v + 1e-5f);
#pragma unroll
    for (int j = 0; j < 4; j++) {
        int d = lane + 32 * j;
        float y = (acc[j] - m) * rstd * g[d] + beta[d];
        g_h[warp * DD + d] = fmaxf(y, 0.0f);
    }
}

// ---------------- edge encoder -> g_ef2[slot], bf16 m16n8k16 fragment layout -------
__global__ void edge_enc_kernel(const float* __restrict__ ea,
                                const float* __restrict__ W,
                                const float* __restrict__ b,
                                const float* __restrict__ g,
                                const float* __restrict__ beta) {
    int warp = (blockIdx.x * blockDim.x + threadIdx.x) >> 5;
    int lane = threadIdx.x & 31;
    if (warp >= EE) return;
    float a0 = b[lane], a1 = b[lane + 32];
#pragma unroll
    for (int k = 0; k < 3; k++) {
        float xv = ea[warp * 3 + k];
        a0 += xv * W[k * EH + lane];
        a1 += xv * W[k * EH + 32 + lane];
    }
    float m = warp_sum(a0 + a1) * (1.0f / EH);
    float d0v = a0 - m, d1v = a1 - m;
    float v = warp_sum(d0v * d0v + d1v * d1v) * (1.0f / EH);
    float rstd = rsqrtf(v + 1e-5f);
    float y0 = fmaxf(d0v * rstd * g[lane] + beta[lane], 0.f);
    float y1 = fmaxf(d1v * rstd * g[lane + 32] + beta[lane + 32], 0.f);

    int L = lane & 15;
    int gk = L >> 2, q = L & 3;
    int d0 = gk * 16 + 2 * q;
    int d1 = d0 + 1, d2 = d0 + 8, d3 = d0 + 9;
    float s0a = __shfl_sync(0xffffffffu, y0, d0 & 31);
    float s0b = __shfl_sync(0xffffffffu, y1, d0 & 31);
    float s1a = __shfl_sync(0xffffffffu, y0, d1 & 31);
    float s1b = __shfl_sync(0xffffffffu, y1, d1 & 31);
    float s2a = __shfl_sync(0xffffffffu, y0, d2 & 31);
    float s2b = __shfl_sync(0xffffffffu, y1, d2 & 31);
    float s3a = __shfl_sync(0xffffffffu, y0, d3 & 31);
    float s3b = __shfl_sync(0xffffffffu, y1, d3 & 31);
    if (lane < 16) {
        float v0 = (d0 < 32) ? s0a : s0b;
        float v1 = (d1 < 32) ? s1a : s1b;
        float v2 = (d2 < 32) ? s2a : s2b;
        float v3 = (d3 < 32) ? s3a : s3b;
        int slot = g_slot[warp];
        g_ef2[(size_t)slot * 16 + L] =
            pack2u(pack_bf2(v0, v1), pack_bf2(v2, v3));
    }
}

// ---------------- CSR build (once per launch) --------------------------------------
__global__ void csr_zero_kernel() {
    int i = blockIdx.x * blockDim.x + threadIdx.x;
    if (i < NN) g_cnt[i] = 0;
}
__global__ void csr_count_kernel(const int* __restrict__ ei) {
    int e = blockIdx.x * blockDim.x + threadIdx.x;
    if (e < EE) atomicAdd(&g_cnt[ei[EE + e]], 1);
}
__global__ void csr_scan_kernel() {
    __shared__ int warpsum[32];
    __shared__ int s_total;
    int tid = threadIdx.x, lane = tid & 31, wid = tid >> 5;
    if (tid == 0) { s_total = 0; g_rowptr[0] = 0; }
    __syncthreads();
    for (int base = 0; base < NN; base += 1024) {
        int i = base + tid;
        int v = (i < NN) ? g_cnt[i] : 0;
        int x = v;
#pragma unroll
        for (int o = 1; o < 32; o <<= 1) {
            int t = __shfl_up_sync(0xffffffffu, x, o);
            if (lane >= o) x += t;
        }
        if (lane == 31) warpsum[wid] = x;
        __syncthreads();
        if (wid == 0) {
            int w = warpsum[lane];
#pragma unroll
            for (int o = 1; o < 32; o <<= 1) {
                int t = __shfl_up_sync(0xffffffffu, w, o);
                if (lane >= o) w += t;
            }
            warpsum[lane] = w;
        }
        __syncthreads();
        int incl = s_total + (wid ? warpsum[wid - 1] : 0) + x;
        if (i < NN) {
            g_rowptr[i + 1] = incl;
            g_wptr[i] = incl - v;
        }
        __syncthreads();
        if (tid == 0) s_total += warpsum[31];
        __syncthreads();
    }
}
__global__ void csr_scatter_kernel(const int* __restrict__ ei) {
    int e = blockIdx.x * blockDim.x + threadIdx.x;
    if (e < EE) {
        int d = ei[EE + e];
        int pos = atomicAdd(&g_wptr[d], 1);
        g_csr[pos] = make_int2(e, ei[e]);
        g_csr_dst[pos] = d;
        g_slot[e] = pos;
    }
}

// ---------------- xl/xr GEMM: bf16 m16n8k16 tensor cores, 64 rows/block, K=128 -----
#define LIN_ROWS 64
#define LKSB 36   // u64 stride per row: 32 frags (8 k-groups x 4) + 4 pad
#define LIN_SMEM ((LIN_ROWS + DD) * LKSB * 8)
__global__ __launch_bounds__(256, 3) void lin_kernel(
    const float* __restrict__ Wl, const float* __restrict__ bl,
    const float* __restrict__ Wr, const float* __restrict__ br) {
    extern __shared__ char smem_raw[];
    u64* sA = (u64*)smem_raw;                          // [64 rows][LKSB]
    u64* sW = (u64*)(smem_raw + LIN_ROWS * LKSB * 8);  // [128 n][LKSB]
    const float* W  = blockIdx.y ? Wr : Wl;
    const float* bv = blockIdx.y ? br : bl;
    float* dst = blockIdx.y ? g_xr : g_xl;
    uint32_t* dsth = blockIdx.y ? g_xrh : g_xlh;
    int m0 = blockIdx.x * LIN_ROWS;
    int tid = threadIdx.x;

    for (int idx = tid; idx < LIN_ROWS * (DD / 16); idx += 256) {
        int r = idx >> 3, gk = idx & 7;
        int gm = m0 + r;
        float4 v0 = make_float4(0.f, 0.f, 0.f, 0.f), v1 = v0, v2 = v0, v3 = v0;
        if (gm < NN) {
            const float* hp = &g_h[(size_t)gm * DD + gk * 16];
            v0 = *(const float4*)&hp[0];
            v1 = *(const float4*)&hp[4];
            v2 = *(const float4*)&hp[8];
            v3 = *(const float4*)&hp[12];
        }
        u64* d = sA + r * LKSB + gk * 4;
        d[0] = pack2u(pack_bf2(v0.x, v0.y), pack_bf2(v2.x, v2.y));
        d[1] = pack2u(pack_bf2(v0.z, v0.w), pack_bf2(v2.z, v2.w));
        d[2] = pack2u(pack_bf2(v1.x, v1.y), pack_bf2(v3.x, v3.y));
        d[3] = pack2u(pack_bf2(v1.z, v1.w), pack_bf2(v3.z, v3.w));
    }
    for (int idx = tid; idx < DD * (DD / 16); idx += 256) {
        int n = idx & 127, gk = idx >> 7;
        float w[16];
#pragma unroll
        for (int j = 0; j < 16; j++) w[j] = W[(gk * 16 + j) * DD + n];
#pragma unroll
        for (int q = 0; q < 4; q++)
            sW[n * LKSB + gk * 4 + q] =
                pack2u(pack_bf2(w[2 * q], w[2 * q + 1]),
                       pack_bf2(w[2 * q + 8], w[2 * q + 9]));
    }
    __syncthreads();

    int lane = tid & 31, wm = tid >> 5;
    int gid = lane >> 2, q = lane & 3;
    int row_base = (wm & 3) * 16;
    int n_base = (wm >> 2) * 64;
    int r0 = row_base + gid, r1 = r0 + 8;
    const u64* ar0 = sA + r0 * LKSB;
    const u64* ar1 = sA + r1 * LKSB;

    float d[8][4];
#pragma unroll
    for (int n8 = 0; n8 < 8; n8++)
#pragma unroll
        for (int j = 0; j < 4; j++) d[n8][j] = 0.f;

#pragma unroll
    for (int gk = 0; gk < 8; gk++) {
        u64 pa0 = ar0[gk * 4 + q];
        u64 pa1 = ar1[gk * 4 + q];
        uint32_t a0 = (uint32_t)pa0, a2 = (uint32_t)(pa0 >> 32);
        uint32_t a1 = (uint32_t)pa1, a3 = (uint32_t)(pa1 >> 32);
#pragma unroll
        for (int n8 = 0; n8 < 8; n8++) {
            u64 pb = sW[(n_base + n8 * 8 + gid) * LKSB + gk * 4 + q];
            uint32_t b0 = (uint32_t)pb, b1 = (uint32_t)(pb >> 32);
            asm volatile(
                "mma.sync.aligned.m16n8k16.row.col.f32.bf16.bf16.f32 "
                "{%0,%1,%2,%3}, {%4,%5,%6,%7}, {%8,%9}, {%0,%1,%2,%3};"
                : "+f"(d[n8][0]), "+f"(d[n8][1]), "+f"(d[n8][2]), "+f"(d[n8][3])
                : "r"(a0), "r"(a1), "r"(a2), "r"(a3), "r"(b0), "r"(b1));
        }
    }

    int gm0 = m0 + r0, gm1 = m0 + r1;
#pragma unroll
    for (int n8 = 0; n8 < 8; n8++) {
        int c = n_base + n8 * 8 + 2 * q;
        float2 bb = *(const float2*)&bv[c];
        if (gm0 < NN) {
            float2 o = make_float2(d[n8][0] + bb.x, d[n8][1] + bb.y);
            *(float2*)&dst[(size_t)gm0 * DD + c] = o;
            dsth[(size_t)gm0 * 64 + (c >> 1)] = pack_bf2(o.x, o.y);
        }
        if (gm1 < NN) {
            float2 o = make_float2(d[n8][2] + bb.x, d[n8][3] + bb.y);
            *(float2*)&dst[(size_t)gm1 * DD + c] = o;
            dsth[(size_t)gm1 * 64 + (c >> 1)] = pack_bf2(o.x, o.y);
        }
    }
}

// ---------------- pass A: bf16 m16n8k16 TC ee GEMM + logits + exp ------------------
#define PA_EDGES 128
#define EFSB 20   // u64 stride per row: 16 frags + 4 pad
#define PASSA_SMEM (PA_EDGES * EFSB * 8 + DD * EFSB * 8 + DD * 4)
__global__ __launch_bounds__(256, 4) void passA_kernel(const float* __restrict__ We,
                                                       const float* __restrict__ att) {
    extern __shared__ char smem_raw[];
    u64*   sEf = (u64*)smem_raw;                            // [128 rows][EFSB]
    u64*   sWe = (u64*)(smem_raw + PA_EDGES * EFSB * 8);    // [128 n][EFSB]
    float* sAtt = (float*)(smem_raw + PA_EDGES * EFSB * 8 + DD * EFSB * 8);
    __shared__ int sSrc[PA_EDGES], sDst[PA_EDGES];
    int tid = threadIdx.x;
    int eb = blockIdx.x * PA_EDGES;

    if (tid < PA_EDGES) {
        sSrc[tid] = g_csr[eb + tid].y;
        sDst[tid] = g_csr_dst[eb + tid];
    }
    if (tid < DD) sAtt[tid] = att[tid];
    for (int idx = tid; idx < DD * (EH / 16); idx += 256) {
        int n = idx & 127, gk = idx >> 7;
        float w[16];
#pragma unroll
        for (int j = 0; j < 16; j++) w[j] = We[(gk * 16 + j) * DD + n];
#pragma unroll
        for (int q = 0; q < 4; q++)
            sWe[n * EFSB + gk * 4 + q] =
                pack2u(pack_bf2(w[2 * q], w[2 * q + 1]),
                       pack_bf2(w[2 * q + 8], w[2 * q + 9]));
    }
    for (int idx = tid; idx < PA_EDGES * 8; idx += 256) {
        int r = idx >> 3, c2 = (idx & 7) << 1;
        uint4 v = *(const uint4*)&g_ef2[(size_t)(eb + r) * 16 + c2];
        *(uint4*)&sEf[r * EFSB + c2] = v;
    }
    __syncthreads();

    int lane = tid & 31, wm = tid >> 5;
    int gid = lane >> 2, q = lane & 3;

    int r0 = wm * 16 + gid;
    int r1 = r0 + 8;
    const uint32_t* xl0h = g_xlh + (size_t)sSrc[r0] * 64;
    const uint32_t* xr0h = g_xrh + (size_t)sDst[r0] * 64;
    const uint32_t* xl1h = g_xlh + (size_t)sSrc[r1] * 64;
    const uint32_t* xr1h = g_xrh + (size_t)sDst[r1] * 64;

    u64 A0[4], A1[4];
    {
        const u64* efr0 = sEf + r0 * EFSB;
        const u64* efr1 = sEf + r1 * EFSB;
#pragma unroll
        for (int gk = 0; gk < 4; gk++) {
            A0[gk] = efr0[gk * 4 + q];
            A1[gk] = efr1[gk * 4 + q];
        }
    }

    float h0[8], h1[8];
#pragma unroll
    for (int h = 0; h < 8; h++) { h0[h] = 0.f; h1[h] = 0.f; }

#pragma unroll
    for (int half = 0; half < 2; half++) {
        float d[8][4];
#pragma unroll
        for (int n8 = 0; n8 < 8; n8++)
#pragma unroll
            for (int j = 0; j < 4; j++) d[n8][j] = 0.f;

#pragma unroll
        for (int gk = 0; gk < 4; gk++) {
            uint32_t a0 = (uint32_t)A0[gk], a2 = (uint32_t)(A0[gk] >> 32);
            uint32_t a1 = (uint32_t)A1[gk], a3 = (uint32_t)(A1[gk] >> 32);
#pragma unroll
            for (int n8 = 0; n8 < 8; n8++) {
                int n = half * 8 + n8;
                u64 pb = sWe[(n * 8 + gid) * EFSB + gk * 4 + q];
                uint32_t b0 = (uint32_t)pb, b1 = (uint32_t)(pb >> 32);
                asm volatile(
                    "mma.sync.aligned.m16n8k16.row.col.f32.bf16.bf16.f32 "
                    "{%0,%1,%2,%3}, {%4,%5,%6,%7}, {%8,%9}, {%0,%1,%2,%3};"
                    : "+f"(d[n8][0]), "+f"(d[n8][1]), "+f"(d[n8][2]), "+f"(d[n8][3])
                    : "r"(a0), "r"(a1), "r"(a2), "r"(a3), "r"(b0), "r"(b1));
            }
        }
#pragma unroll
        for (int n8 = 0; n8 < 8; n8++) {
            int n = half * 8 + n8;
            int ci = n * 4 + q;
            float2 av = *(const float2*)&sAtt[n * 8 + q * 2];
            float2 l0v = unpack_bf2(xl0h[ci]);
            float2 r0v = unpack_bf2(xr0h[ci]);
            float2 l1v = unpack_bf2(xl1h[ci]);
            float2 r1v = unpack_bf2(xr1h[ci]);
            float v00 = d[n8][0] + l0v.x + r0v.x; v00 = v00 > 0.f ? v00 : 0.2f * v00;
            float v01 = d[n8][1] + l0v.y + r0v.y; v01 = v01 > 0.f ? v01 : 0.2f * v01;
            float v10 = d[n8][2] + l1v.x + r1v.x; v10 = v10 > 0.f ? v10 : 0.2f * v10;
            float v11 = d[n8][3] + l1v.y + r1v.y; v11 = v11 > 0.f ? v11 : 0.2f * v11;
            h0[n >> 1] += v00 * av.x + v01 * av.y;
            h1[n >> 1] += v10 * av.x + v11 * av.y;
        }
    }
#pragma unroll
    for (int h = 0; h < 8; h++) {
        h0[h] += __shfl_xor_sync(0xffffffffu, h0[h], 1);
        h0[h] += __shfl_xor_sync(0xffffffffu, h0[h], 2);
        h1[h] += __shfl_xor_sync(0xffffffffu, h1[h], 1);
        h1[h] += __shfl_xor_sync(0xffffffffu, h1[h], 2);
    }
    size_t p0 = (size_t)(eb + r0) * HH;
    size_t p1 = (size_t)(eb + r1) * HH;
    g_a[p0 + 2 * q]     = expf(h0[2 * q]);
    g_a[p0 + 2 * q + 1] = expf(h0[2 * q + 1]);
    g_a[p1 + 2 * q]     = expf(h1[2 * q]);
    g_a[p1 + 2 * q + 1] = expf(h1[2 * q + 1]);
}

// ---------------- pass B: per-dst gather (bf16 xl mirror) + residual+LN+relu -------
__global__ void passB_kernel(const float* __restrict__ cb,
                             const float* __restrict__ g,
                             const float* __restrict__ beta) {
    int node = (blockIdx.x * blockDim.x + threadIdx.x) >> 5;
    int lane = threadIdx.x & 31;
    if (node >= NN) return;
    int start = g_rowptr[node], end = g_rowptr[node + 1];

    float s = 0.f;
    for (int p0 = start; p0 < end; p0 += 4) {
        int p = p0 + (lane >> 3);
        if (p < end) s += g_a[(size_t)p * HH + (lane & 7)];
    }
    s += __shfl_xor_sync(0xffffffffu, s, 8);
    s += __shfl_xor_sync(0xffffffffu, s, 16);
    float sh = __shfl_sync(0xffffffffu, s, lane >> 2);
    float rinv = 1.0f / (sh + 1e-16f);

    int head = lane >> 2;
    // lane covers dims [4*lane, 4*lane+4) -> bf16x2 words 2*lane, 2*lane+1
    float4 acc = make_float4(0.f, 0.f, 0.f, 0.f);
    int p = start;
    for (; p + 4 <= end; p += 4) {
        int s0 = g_csr[p].y,     s1 = g_csr[p + 1].y;
        int s2 = g_csr[p + 2].y, s3 = g_csr[p + 3].y;
        float a0 = g_a[(size_t)(p)     * HH + head];
        float a1 = g_a[(size_t)(p + 1) * HH + head];
        float a2 = g_a[(size_t)(p + 2) * HH + head];
        float a3 = g_a[(size_t)(p + 3) * HH + head];
        uint2 u0 = *(const uint2*)&g_xlh[(size_t)s0 * 64 + 2 * lane];
        uint2 u1 = *(const uint2*)&g_xlh[(size_t)s1 * 64 + 2 * lane];
        uint2 u2 = *(const uint2*)&g_xlh[(size_t)s2 * 64 + 2 * lane];
        uint2 u3 = *(const uint2*)&g_xlh[(size_t)s3 * 64 + 2 * lane];
        float2 x0a = unpack_bf2(u0.x), x0b = unpack_bf2(u0.y);
        float2 x1a = unpack_bf2(u1.x), x1b = unpack_bf2(u1.y);
        float2 x2a = unpack_bf2(u2.x), x2b = unpack_bf2(u2.y);
        float2 x3a = unpack_bf2(u3.x), x3b = unpack_bf2(u3.y);
        acc.x += a0 * x0a.x + a1 * x1a.x + a2 * x2a.x + a3 * x3a.x;
        acc.y += a0 * x0a.y + a1 * x1a.y + a2 * x2a.y + a3 * x3a.y;
        acc.z += a0 * x0b.x + a1 * x1b.x + a2 * x2b.x + a3 * x3b.x;
        acc.w += a0 * x0b.y + a1 * x1b.y + a2 * x2b.y + a3 * x3b.y;
    }
    for (; p < end; p++) {
        int sn = g_csr[p].y;
        float al = g_a[(size_t)p * HH + head];
        uint2 u = *(const uint2*)&g_xlh[(size_t)sn * 64 + 2 * lane];
        float2 xa = unpack_bf2(u.x), xb = unpack_bf2(u.y);
        acc.x += al * xa.x; acc.y += al * xa.y;
        acc.z += al * xb.x; acc.w += al * xb.y;
    }
    acc.x *= rinv; acc.y *= rinv; acc.z *= rinv; acc.w *= rinv;

    int d0 = 4 * lane;
    float4 hv = *(const float4*)&g_h[node * DD + d0];
    float4 cv = *(const float4*)&cb[d0];
    float a0 = acc.x + cv.x + hv.x;
    float a1 = acc.y + cv.y + hv.y;
    float a2 = acc.z + cv.z + hv.z;
    float a3 = acc.w + cv.w + hv.w;
    float m = warp_sum(a0 + a1 + a2 + a3) * (1.0f / DD);
    float e0d = a0 - m, e1d = a1 - m, e2d = a2 - m, e3d = a3 - m;
    float v = warp_sum(e0d * e0d + e1d * e1d + e2d * e2d + e3d * e3d) * (1.0f / DD);
    float rstd = rsqrtf(v + 1e-5f);
    float4 gv = *(const float4*)&g[d0];
    float4 bv = *(const float4*)&beta[d0];
    float4 o;
    o.x = fmaxf(e0d * rstd * gv.x + bv.x, 0.f);
    o.y = fmaxf(e1d * rstd * gv.y + bv.y, 0.f);
    o.z = fmaxf(e2d * rstd * gv.z + bv.z, 0.f);
    o.w = fmaxf(e3d * rstd * gv.w + bv.w, 0.f);
    *(float4*)&g_h[node * DD + d0] = o;
}

// ---------------- head: relu(h@W1+b1) @ W2 -> sigmoid. 1 warp/node -----------------
__global__ void head_kernel(float* __restrict__ out,
                            const float* __restrict__ W1, const float* __restrict__ b1,
                            const float* __restrict__ W2, const float* __restrict__ b2) {
    int warp = (blockIdx.x * blockDim.x + threadIdx.x) >> 5;
    int lane = threadIdx.x & 31;
    if (warp >= NN) return;
    float hr[4];
#pragma unroll
    for (int q = 0; q < 4; q++) hr[q] = g_h[warp * DD + q * 32 + lane];
    float z0 = b1[lane], z1 = b1[lane + 32];
#pragma unroll
    for (int q = 0; q < 4; q++) {
#pragma unroll 8
        for (int kk = 0; kk < 32; kk++) {
            float hk = __shfl_sync(0xffffffffu, hr[q], kk);
            int k = q * 32 + kk;
            z0 += hk * W1[k * 64 + lane];
            z1 += hk * W1[k * 64 + 32 + lane];
        }
    }
    z0 = fmaxf(z0, 0.f);
    z1 = fmaxf(z1, 0.f);
    float p = z0 * W2[lane] + z1 * W2[lane + 32];
    p = warp_sum(p);
    if (lane == 0) out[warp] = 1.0f / (1.0f + expf(-(p + b2[0])));
}

// ---------------- launch ----------------------------------------------------------
extern "C" void kernel_launch(void* const* d_in, const int* in_sizes, int n_in,
                              void* d_out, int out_size) {
    const float* x    = (const float*)d_in[0];
    const int*   ei   = (const int*)  d_in[1];
    const float* ea   = (const float*)d_in[2];
    const float* neW  = (const float*)d_in[3];
    const float* neb  = (const float*)d_in[4];
    const float* neg  = (const float*)d_in[5];
    const float* nebt = (const float*)d_in[6];
    const float* eeW  = (const float*)d_in[7];
    const float* eeb  = (const float*)d_in[8];
    const float* eeg  = (const float*)d_in[9];
    const float* eebt = (const float*)d_in[10];
    const float* Wl   = (const float*)d_in[11];
    const float* bl   = (const float*)d_in[12];
    const float* Wr   = (const float*)d_in[13];
    const float* br   = (const float*)d_in[14];
    const float* We   = (const float*)d_in[15];
    const float* att  = (const float*)d_in[16];
    const float* cb   = (const float*)d_in[17];
    const float* lng  = (const float*)d_in[18];
    const float* lnb  = (const float*)d_in[19];
    const float* W1   = (const float*)d_in[20];
    const float* b1   = (const float*)d_in[21];
    const float* W2   = (const float*)d_in[22];
    const float* b2   = (const float*)d_in[23];
    float* out = (float*)d_out;

    cudaFuncSetAttribute(lin_kernel, cudaFuncAttributeMaxDynamicSharedMemorySize,
                         LIN_SMEM);
    cudaFuncSetAttribute(passA_kernel, cudaFuncAttributeMaxDynamicSharedMemorySize,
                         PASSA_SMEM);

    dim3 lin_grid((NN + LIN_ROWS - 1) / LIN_ROWS, 2);
    int passa_grid = EE / PA_EDGES;

    node_enc_kernel<<<NN / 8, 256>>>(x, neW, neb, neg, nebt);                    // 0
    csr_zero_kernel<<<(NN + 255) / 256, 256>>>();                                // 1
    csr_count_kernel<<<(EE + 255) / 256, 256>>>(ei);                             // 2
    lin_kernel<<<lin_grid, 256, LIN_SMEM>>>(Wl, bl, Wr, br);                     // 3 (profiled; control)
    csr_scan_kernel<<<1, 1024>>>();                                              // 4
    csr_scatter_kernel<<<(EE + 255) / 256, 256>>>(ei);                           // 5
    edge_enc_kernel<<<EE / 8, 256>>>(ea, eeW, eeb, eeg, eebt);                   // 6 (needs g_slot)

    for (int l = 0; l < LL; l++) {
        if (l > 0)
            lin_kernel<<<lin_grid, 256, LIN_SMEM>>>(Wl + l * DD * DD, bl + l * DD,
                                                    Wr + l * DD * DD, br + l * DD);
        passA_kernel<<<passa_grid, 256, PASSA_SMEM>>>(We + l * EH * DD,
                                                      att + l * HH * CC);
        passB_kernel<<<(NN * 32 + 255) / 256, 256>>>(cb + l * DD, lng + l * DD,
                                                     lnb + l * DD);
    }
    head_kernel<<<NN / 8, 256>>>(out, W1, b1, W2, b2);
}

// round 16
// speedup vs baseline: 1.4315x; 1.0539x over previous
#include <cuda_runtime.h>
#include <math.h>
#include <stdint.h>

#define NN 50000
#define EE 400000
#define DD 128
#define HH 8
#define CC 16
#define EH 64
#define LL 6

static_assert(EE % 128 == 0, "edge tiling");
static_assert(NN % 8 == 0, "node tiling");

typedef unsigned long long u64;

// ---------------- device scratch (static; no allocations allowed) ----------------
__device__ __align__(16) float g_h  [NN * DD];   // node features
__device__ __align__(8) uint32_t g_xlh[NN * 64]; // bf16x2 xl (sole representation)
__device__ __align__(8) uint32_t g_xrh[NN * 64]; // bf16x2 xr (sole representation)
__device__ __align__(16) u64 g_ef2[EE * 16];     // ef, CSR-slot order, bf16 m16n8k16 frags
__device__             float g_a   [EE * HH];    // exp(logit), indexed by CSR SLOT
// CSR by destination node (built once per launch)
__device__ int  g_cnt   [NN];
__device__ int  g_wptr  [NN];
__device__ int  g_rowptr[NN + 1];
__device__ int2 g_csr    [EE];   // (orig edge id, src node) per slot
__device__ int  g_csr_dst[EE];   // dst node per slot
__device__ int  g_slot   [EE];   // edge id -> CSR slot (inverse map)

__device__ __forceinline__ float warp_sum(float v) {
#pragma unroll
    for (int o = 16; o; o >>= 1) v += __shfl_xor_sync(0xffffffffu, v, o);
    return v;
}
__device__ __forceinline__ u64 pack2u(uint32_t lo, uint32_t hi) {
    return ((u64)hi << 32) | (u64)lo;
}
__device__ __forceinline__ uint32_t pack_bf2(float lo, float hi) {
    uint32_t r;
    asm("cvt.rn.bf16x2.f32 %0, %1, %2;" : "=r"(r) : "f"(hi), "f"(lo));
    return r;
}
__device__ __forceinline__ float2 unpack_bf2(uint32_t u) {
    float2 r;
    r.x = __uint_as_float(u << 16);
    r.y = __uint_as_float(u & 0xffff0000u);
    return r;
}

// ---------------- node encoder: x(N,9) -> LN -> relu -> g_h(N,128). 1 warp/node ----
__global__ void node_enc_kernel(const float* __restrict__ x,
                                const float* __restrict__ W,
                                const float* __restrict__ b,
                                const float* __restrict__ g,
                                const float* __restrict__ beta) {
    int warp = (blockIdx.x * blockDim.x + threadIdx.x) >> 5;
    int lane = threadIdx.x & 31;
    if (warp >= NN) return;
    float acc[4];
#pragma unroll
    for (int j = 0; j < 4; j++) acc[j] = b[lane + 32 * j];
#pragma unroll
    for (int k = 0; k < 9; k++) {
        float xv = x[warp * 9 + k];
#pragma unroll
        for (int j = 0; j < 4; j++) acc[j] += xv * W[k * DD + lane + 32 * j];
    }
    float s = 0.f;
#pragma unroll
    for (int j = 0; j < 4; j++) s += acc[j];
    float m = warp_sum(s) * (1.0f / DD);
    float v = 0.f;
#pragma unroll
    for (int j = 0; j < 4; j++) { float d = acc[j] - m; v += d * d; }
    v = warp_sum(v) * (1.0f / DD);
    float rstd = rsqrtf(v + 1e-5f);
#pragma unroll
    for (int j = 0; j < 4; j++) {
        int d = lane + 32 * j;
        float y = (acc[j] - m) * rstd * g[d] + beta[d];
        g_h[warp * DD + d] = fmaxf(y, 0.0f);
    }
}

// ---------------- edge encoder -> g_ef2[slot], bf16 m16n8k16 fragment layout -------
__global__ void edge_enc_kernel(const float* __restrict__ ea,
                                const float* __restrict__ W,
                                const float* __restrict__ b,
                                const float* __restrict__ g,
                                const float* __restrict__ beta) {
    int warp = (blockIdx.x * blockDim.x + threadIdx.x) >> 5;
    int lane = threadIdx.x & 31;
    if (warp >= EE) return;
    float a0 = b[lane], a1 = b[lane + 32];
#pragma unroll
    for (int k = 0; k < 3; k++) {
        float xv = ea[warp * 3 + k];
        a0 += xv * W[k * EH + lane];
        a1 += xv * W[k * EH + 32 + lane];
    }
    float m = warp_sum(a0 + a1) * (1.0f / EH);
    float d0v = a0 - m, d1v = a1 - m;
    float v = warp_sum(d0v * d0v + d1v * d1v) * (1.0f / EH);
    float rstd = rsqrtf(v + 1e-5f);
    float y0 = fmaxf(d0v * rstd * g[lane] + beta[lane], 0.f);
    float y1 = fmaxf(d1v * rstd * g[lane + 32] + beta[lane + 32], 0.f);

    int L = lane & 15;
    int gk = L >> 2, q = L & 3;
    int d0 = gk * 16 + 2 * q;
    int d1 = d0 + 1, d2 = d0 + 8, d3 = d0 + 9;
    float s0a = __shfl_sync(0xffffffffu, y0, d0 & 31);
    float s0b = __shfl_sync(0xffffffffu, y1, d0 & 31);
    float s1a = __shfl_sync(0xffffffffu, y0, d1 & 31);
    float s1b = __shfl_sync(0xffffffffu, y1, d1 & 31);
    float s2a = __shfl_sync(0xffffffffu, y0, d2 & 31);
    float s2b = __shfl_sync(0xffffffffu, y1, d2 & 31);
    float s3a = __shfl_sync(0xffffffffu, y0, d3 & 31);
    float s3b = __shfl_sync(0xffffffffu, y1, d3 & 31);
    if (lane < 16) {
        float v0 = (d0 < 32) ? s0a : s0b;
        float v1 = (d1 < 32) ? s1a : s1b;
        float v2 = (d2 < 32) ? s2a : s2b;
        float v3 = (d3 < 32) ? s3a : s3b;
        int slot = g_slot[warp];
        g_ef2[(size_t)slot * 16 + L] =
            pack2u(pack_bf2(v0, v1), pack_bf2(v2, v3));
    }
}

// ---------------- CSR build (once per launch) --------------------------------------
__global__ void csr_zero_kernel() {
    int i = blockIdx.x * blockDim.x + threadIdx.x;
    if (i < NN) g_cnt[i] = 0;
}
__global__ void csr_count_kernel(const int* __restrict__ ei) {
    int e = blockIdx.x * blockDim.x + threadIdx.x;
    if (e < EE) atomicAdd(&g_cnt[ei[EE + e]], 1);
}
__global__ void csr_scan_kernel() {
    __shared__ int warpsum[32];
    __shared__ int s_total;
    int tid = threadIdx.x, lane = tid & 31, wid = tid >> 5;
    if (tid == 0) { s_total = 0; g_rowptr[0] = 0; }
    __syncthreads();
    for (int base = 0; base < NN; base += 1024) {
        int i = base + tid;
        int v = (i < NN) ? g_cnt[i] : 0;
        int x = v;
#pragma unroll
        for (int o = 1; o < 32; o <<= 1) {
            int t = __shfl_up_sync(0xffffffffu, x, o);
            if (lane >= o) x += t;
        }
        if (lane == 31) warpsum[wid] = x;
        __syncthreads();
        if (wid == 0) {
            int w = warpsum[lane];
#pragma unroll
            for (int o = 1; o < 32; o <<= 1) {
                int t = __shfl_up_sync(0xffffffffu, w, o);
                if (lane >= o) w += t;
            }
            warpsum[lane] = w;
        }
        __syncthreads();
        int incl = s_total + (wid ? warpsum[wid - 1] : 0) + x;
        if (i < NN) {
            g_rowptr[i + 1] = incl;
            g_wptr[i] = incl - v;
        }
        __syncthreads();
        if (tid == 0) s_total += warpsum[31];
        __syncthreads();
    }
}
__global__ void csr_scatter_kernel(const int* __restrict__ ei) {
    int e = blockIdx.x * blockDim.x + threadIdx.x;
    if (e < EE) {
        int d = ei[EE + e];
        int pos = atomicAdd(&g_wptr[d], 1);
        g_csr[pos] = make_int2(e, ei[e]);
        g_csr_dst[pos] = d;
        g_slot[e] = pos;
    }
}

// ---------------- xl/xr GEMM: bf16 m16n8k16 TC; bf16 mirror outputs ONLY -----------
#define LIN_ROWS 64
#define LKSB 36   // u64 stride per row: 32 frags (8 k-groups x 4) + 4 pad
#define LIN_SMEM ((LIN_ROWS + DD) * LKSB * 8)
__global__ __launch_bounds__(256, 3) void lin_kernel(
    const float* __restrict__ Wl, const float* __restrict__ bl,
    const float* __restrict__ Wr, const float* __restrict__ br) {
    extern __shared__ char smem_raw[];
    u64* sA = (u64*)smem_raw;                          // [64 rows][LKSB]
    u64* sW = (u64*)(smem_raw + LIN_ROWS * LKSB * 8);  // [128 n][LKSB]
    const float* W  = blockIdx.y ? Wr : Wl;
    const float* bv = blockIdx.y ? br : bl;
    uint32_t* dsth = blockIdx.y ? g_xrh : g_xlh;
    int m0 = blockIdx.x * LIN_ROWS;
    int tid = threadIdx.x;

    for (int idx = tid; idx < LIN_ROWS * (DD / 16); idx += 256) {
        int r = idx >> 3, gk = idx & 7;
        int gm = m0 + r;
        float4 v0 = make_float4(0.f, 0.f, 0.f, 0.f), v1 = v0, v2 = v0, v3 = v0;
        if (gm < NN) {
            const float* hp = &g_h[(size_t)gm * DD + gk * 16];
            v0 = *(const float4*)&hp[0];
            v1 = *(const float4*)&hp[4];
            v2 = *(const float4*)&hp[8];
            v3 = *(const float4*)&hp[12];
        }
        u64* d = sA + r * LKSB + gk * 4;
        d[0] = pack2u(pack_bf2(v0.x, v0.y), pack_bf2(v2.x, v2.y));
        d[1] = pack2u(pack_bf2(v0.z, v0.w), pack_bf2(v2.z, v2.w));
        d[2] = pack2u(pack_bf2(v1.x, v1.y), pack_bf2(v3.x, v3.y));
        d[3] = pack2u(pack_bf2(v1.z, v1.w), pack_bf2(v3.z, v3.w));
    }
    for (int idx = tid; idx < DD * (DD / 16); idx += 256) {
        int n = idx & 127, gk = idx >> 7;
        float w[16];
#pragma unroll
        for (int j = 0; j < 16; j++) w[j] = W[(gk * 16 + j) * DD + n];
#pragma unroll
        for (int q = 0; q < 4; q++)
            sW[n * LKSB + gk * 4 + q] =
                pack2u(pack_bf2(w[2 * q], w[2 * q + 1]),
                       pack_bf2(w[2 * q + 8], w[2 * q + 9]));
    }
    __syncthreads();

    int lane = tid & 31, wm = tid >> 5;
    int gid = lane >> 2, q = lane & 3;
    int row_base = (wm & 3) * 16;
    int n_base = (wm >> 2) * 64;
    int r0 = row_base + gid, r1 = r0 + 8;
    const u64* ar0 = sA + r0 * LKSB;
    const u64* ar1 = sA + r1 * LKSB;

    float d[8][4];
#pragma unroll
    for (int n8 = 0; n8 < 8; n8++)
#pragma unroll
        for (int j = 0; j < 4; j++) d[n8][j] = 0.f;

#pragma unroll
    for (int gk = 0; gk < 8; gk++) {
        u64 pa0 = ar0[gk * 4 + q];
        u64 pa1 = ar1[gk * 4 + q];
        uint32_t a0 = (uint32_t)pa0, a2 = (uint32_t)(pa0 >> 32);
        uint32_t a1 = (uint32_t)pa1, a3 = (uint32_t)(pa1 >> 32);
#pragma unroll
        for (int n8 = 0; n8 < 8; n8++) {
            u64 pb = sW[(n_base + n8 * 8 + gid) * LKSB + gk * 4 + q];
            uint32_t b0 = (uint32_t)pb, b1 = (uint32_t)(pb >> 32);
            asm volatile(
                "mma.sync.aligned.m16n8k16.row.col.f32.bf16.bf16.f32 "
                "{%0,%1,%2,%3}, {%4,%5,%6,%7}, {%8,%9}, {%0,%1,%2,%3};"
                : "+f"(d[n8][0]), "+f"(d[n8][1]), "+f"(d[n8][2]), "+f"(d[n8][3])
                : "r"(a0), "r"(a1), "r"(a2), "r"(a3), "r"(b0), "r"(b1));
        }
    }

    int gm0 = m0 + r0, gm1 = m0 + r1;
#pragma unroll
    for (int n8 = 0; n8 < 8; n8++) {
        int c = n_base + n8 * 8 + 2 * q;
        float2 bb = *(const float2*)&bv[c];
        if (gm0 < NN)
            dsth[(size_t)gm0 * 64 + (c >> 1)] =
                pack_bf2(d[n8][0] + bb.x, d[n8][1] + bb.y);
        if (gm1 < NN)
            dsth[(size_t)gm1 * 64 + (c >> 1)] =
                pack_bf2(d[n8][2] + bb.x, d[n8][3] + bb.y);
    }
}

// ---------------- pass A: bf16 m16n8k16 TC ee GEMM + logits + exp ------------------
#define PA_EDGES 128
#define EFSB 20   // u64 stride per row: 16 frags + 4 pad
#define PASSA_SMEM (PA_EDGES * EFSB * 8 + DD * EFSB * 8 + DD * 4)
__global__ __launch_bounds__(256, 4) void passA_kernel(const float* __restrict__ We,
                                                       const float* __restrict__ att) {
    extern __shared__ char smem_raw[];
    u64*   sEf = (u64*)smem_raw;                            // [128 rows][EFSB]
    u64*   sWe = (u64*)(smem_raw + PA_EDGES * EFSB * 8);    // [128 n][EFSB]
    float* sAtt = (float*)(smem_raw + PA_EDGES * EFSB * 8 + DD * EFSB * 8);
    __shared__ int sSrc[PA_EDGES], sDst[PA_EDGES];
    int tid = threadIdx.x;
    int eb = blockIdx.x * PA_EDGES;

    if (tid < PA_EDGES) {
        sSrc[tid] = g_csr[eb + tid].y;
        sDst[tid] = g_csr_dst[eb + tid];
    }
    if (tid < DD) sAtt[tid] = att[tid];
    for (int idx = tid; idx < DD * (EH / 16); idx += 256) {
        int n = idx & 127, gk = idx >> 7;
        float w[16];
#pragma unroll
        for (int j = 0; j < 16; j++) w[j] = We[(gk * 16 + j) * DD + n];
#pragma unroll
        for (int q = 0; q < 4; q++)
            sWe[n * EFSB + gk * 4 + q] =
                pack2u(pack_bf2(w[2 * q], w[2 * q + 1]),
                       pack_bf2(w[2 * q + 8], w[2 * q + 9]));
    }
    for (int idx = tid; idx < PA_EDGES * 8; idx += 256) {
        int r = idx >> 3, c2 = (idx & 7) << 1;
        uint4 v = *(const uint4*)&g_ef2[(size_t)(eb + r) * 16 + c2];
        *(uint4*)&sEf[r * EFSB + c2] = v;
    }
    __syncthreads();

    int lane = tid & 31, wm = tid >> 5;
    int gid = lane >> 2, q = lane & 3;

    int r0 = wm * 16 + gid;
    int r1 = r0 + 8;
    const uint32_t* xl0h = g_xlh + (size_t)sSrc[r0] * 64;
    const uint32_t* xr0h = g_xrh + (size_t)sDst[r0] * 64;
    const uint32_t* xl1h = g_xlh + (size_t)sSrc[r1] * 64;
    const uint32_t* xr1h = g_xrh + (size_t)sDst[r1] * 64;

    u64 A0[4], A1[4];
    {
        const u64* efr0 = sEf + r0 * EFSB;
        const u64* efr1 = sEf + r1 * EFSB;
#pragma unroll
        for (int gk = 0; gk < 4; gk++) {
            A0[gk] = efr0[gk * 4 + q];
            A1[gk] = efr1[gk * 4 + q];
        }
    }

    float h0[8], h1[8];
#pragma unroll
    for (int h = 0; h < 8; h++) { h0[h] = 0.f; h1[h] = 0.f; }

#pragma unroll
    for (int half = 0; half < 2; half++) {
        float d[8][4];
#pragma unroll
        for (int n8 = 0; n8 < 8; n8++)
#pragma unroll
            for (int j = 0; j < 4; j++) d[n8][j] = 0.f;

#pragma unroll
        for (int gk = 0; gk < 4; gk++) {
            uint32_t a0 = (uint32_t)A0[gk], a2 = (uint32_t)(A0[gk] >> 32);
            uint32_t a1 = (uint32_t)A1[gk], a3 = (uint32_t)(A1[gk] >> 32);
#pragma unroll
            for (int n8 = 0; n8 < 8; n8++) {
                int n = half * 8 + n8;
                u64 pb = sWe[(n * 8 + gid) * EFSB + gk * 4 + q];
                uint32_t b0 = (uint32_t)pb, b1 = (uint32_t)(pb >> 32);
                asm volatile(
                    "mma.sync.aligned.m16n8k16.row.col.f32.bf16.bf16.f32 "
                    "{%0,%1,%2,%3}, {%4,%5,%6,%7}, {%8,%9}, {%0,%1,%2,%3};"
                    : "+f"(d[n8][0]), "+f"(d[n8][1]), "+f"(d[n8][2]), "+f"(d[n8][3])
                    : "r"(a0), "r"(a1), "r"(a2), "r"(a3), "r"(b0), "r"(b1));
            }
        }
#pragma unroll
        for (int n8 = 0; n8 < 8; n8++) {
            int n = half * 8 + n8;
            int ci = n * 4 + q;
            float2 av = *(const float2*)&sAtt[n * 8 + q * 2];
            float2 l0v = unpack_bf2(xl0h[ci]);
            float2 r0v = unpack_bf2(xr0h[ci]);
            float2 l1v = unpack_bf2(xl1h[ci]);
            float2 r1v = unpack_bf2(xr1h[ci]);
            float v00 = d[n8][0] + l0v.x + r0v.x; v00 = v00 > 0.f ? v00 : 0.2f * v00;
            float v01 = d[n8][1] + l0v.y + r0v.y; v01 = v01 > 0.f ? v01 : 0.2f * v01;
            float v10 = d[n8][2] + l1v.x + r1v.x; v10 = v10 > 0.f ? v10 : 0.2f * v10;
            float v11 = d[n8][3] + l1v.y + r1v.y; v11 = v11 > 0.f ? v11 : 0.2f * v11;
            h0[n >> 1] += v00 * av.x + v01 * av.y;
            h1[n >> 1] += v10 * av.x + v11 * av.y;
        }
    }
#pragma unroll
    for (int h = 0; h < 8; h++) {
        h0[h] += __shfl_xor_sync(0xffffffffu, h0[h], 1);
        h0[h] += __shfl_xor_sync(0xffffffffu, h0[h], 2);
        h1[h] += __shfl_xor_sync(0xffffffffu, h1[h], 1);
        h1[h] += __shfl_xor_sync(0xffffffffu, h1[h], 2);
    }
    size_t p0 = (size_t)(eb + r0) * HH;
    size_t p1 = (size_t)(eb + r1) * HH;
    g_a[p0 + 2 * q]     = expf(h0[2 * q]);
    g_a[p0 + 2 * q + 1] = expf(h0[2 * q + 1]);
    g_a[p1 + 2 * q]     = expf(h1[2 * q]);
    g_a[p1 + 2 * q + 1] = expf(h1[2 * q + 1]);
}

// ---------------- pass B: per-dst gather (bf16 xl mirror) + residual+LN+relu -------
__global__ void passB_kernel(const float* __restrict__ cb,
                             const float* __restrict__ g,
                             const float* __restrict__ beta) {
    int node = (blockIdx.x * blockDim.x + threadIdx.x) >> 5;
    int lane = threadIdx.x & 31;
    if (node >= NN) return;
    int start = g_rowptr[node], end = g_rowptr[node + 1];

    float s = 0.f;
    for (int p0 = start; p0 < end; p0 += 4) {
        int p = p0 + (lane >> 3);
        if (p < end) s += g_a[(size_t)p * HH + (lane & 7)];
    }
    s += __shfl_xor_sync(0xffffffffu, s, 8);
    s += __shfl_xor_sync(0xffffffffu, s, 16);
    float sh = __shfl_sync(0xffffffffu, s, lane >> 2);
    float rinv = 1.0f / (sh + 1e-16f);

    int head = lane >> 2;
    float4 acc = make_float4(0.f, 0.f, 0.f, 0.f);
    int p = start;
    for (; p + 4 <= end; p += 4) {
        int s0 = g_csr[p].y,     s1 = g_csr[p + 1].y;
        int s2 = g_csr[p + 2].y, s3 = g_csr[p + 3].y;
        float a0 = g_a[(size_t)(p)     * HH + head];
        float a1 = g_a[(size_t)(p + 1) * HH + head];
        float a2 = g_a[(size_t)(p + 2) * HH + head];
        float a3 = g_a[(size_t)(p + 3) * HH + head];
        uint2 u0 = *(const uint2*)&g_xlh[(size_t)s0 * 64 + 2 * lane];
        uint2 u1 = *(const uint2*)&g_xlh[(size_t)s1 * 64 + 2 * lane];
        uint2 u2 = *(const uint2*)&g_xlh[(size_t)s2 * 64 + 2 * lane];
        uint2 u3 = *(const uint2*)&g_xlh[(size_t)s3 * 64 + 2 * lane];
        float2 x0a = unpack_bf2(u0.x), x0b = unpack_bf2(u0.y);
        float2 x1a = unpack_bf2(u1.x), x1b = unpack_bf2(u1.y);
        float2 x2a = unpack_bf2(u2.x), x2b = unpack_bf2(u2.y);
        float2 x3a = unpack_bf2(u3.x), x3b = unpack_bf2(u3.y);
        acc.x += a0 * x0a.x + a1 * x1a.x + a2 * x2a.x + a3 * x3a.x;
        acc.y += a0 * x0a.y + a1 * x1a.y + a2 * x2a.y + a3 * x3a.y;
        acc.z += a0 * x0b.x + a1 * x1b.x + a2 * x2b.x + a3 * x3b.x;
        acc.w += a0 * x0b.y + a1 * x1b.y + a2 * x2b.y + a3 * x3b.y;
    }
    for (; p < end; p++) {
        int sn = g_csr[p].y;
        float al = g_a[(size_t)p * HH + head];
        uint2 u = *(const uint2*)&g_xlh[(size_t)sn * 64 + 2 * lane];
        float2 xa = unpack_bf2(u.x), xb = unpack_bf2(u.y);
        acc.x += al * xa.x; acc.y += al * xa.y;
        acc.z += al * xb.x; acc.w += al * xb.y;
    }
    acc.x *= rinv; acc.y *= rinv; acc.z *= rinv; acc.w *= rinv;

    int d0 = 4 * lane;
    float4 hv = *(const float4*)&g_h[node * DD + d0];
    float4 cv = *(const float4*)&cb[d0];
    float a0 = acc.x + cv.x + hv.x;
    float a1 = acc.y + cv.y + hv.y;
    float a2 = acc.z + cv.z + hv.z;
    float a3 = acc.w + cv.w + hv.w;
    float m = warp_sum(a0 + a1 + a2 + a3) * (1.0f / DD);
    float e0d = a0 - m, e1d = a1 - m, e2d = a2 - m, e3d = a3 - m;
    float v = warp_sum(e0d * e0d + e1d * e1d + e2d * e2d + e3d * e3d) * (1.0f / DD);
    float rstd = rsqrtf(v + 1e-5f);
    float4 gv = *(const float4*)&g[d0];
    float4 bv = *(const float4*)&beta[d0];
    float4 o;
    o.x = fmaxf(e0d * rstd * gv.x + bv.x, 0.f);
    o.y = fmaxf(e1d * rstd * gv.y + bv.y, 0.f);
    o.z = fmaxf(e2d * rstd * gv.z + bv.z, 0.f);
    o.w = fmaxf(e3d * rstd * gv.w + bv.w, 0.f);
    *(float4*)&g_h[node * DD + d0] = o;
}

// ---------------- head: relu(h@W1+b1) @ W2 -> sigmoid. 1 warp/node -----------------
__global__ void head_kernel(float* __restrict__ out,
                            const float* __restrict__ W1, const float* __restrict__ b1,
                            const float* __restrict__ W2, const float* __restrict__ b2) {
    int warp = (blockIdx.x * blockDim.x + threadIdx.x) >> 5;
    int lane = threadIdx.x & 31;
    if (warp >= NN) return;
    float hr[4];
#pragma unroll
    for (int q = 0; q < 4; q++) hr[q] = g_h[warp * DD + q * 32 + lane];
    float z0 = b1[lane], z1 = b1[lane + 32];
#pragma unroll
    for (int q = 0; q < 4; q++) {
#pragma unroll 8
        for (int kk = 0; kk < 32; kk++) {
            float hk = __shfl_sync(0xffffffffu, hr[q], kk);
            int k = q * 32 + kk;
            z0 += hk * W1[k * 64 + lane];
            z1 += hk * W1[k * 64 + 32 + lane];
        }
    }
    z0 = fmaxf(z0, 0.f);
    z1 = fmaxf(z1, 0.f);
    float p = z0 * W2[lane] + z1 * W2[lane + 32];
    p = warp_sum(p);
    if (lane == 0) out[warp] = 1.0f / (1.0f + expf(-(p + b2[0])));
}

// ---------------- launch ----------------------------------------------------------
extern "C" void kernel_launch(void* const* d_in, const int* in_sizes, int n_in,
                              void* d_out, int out_size) {
    const float* x    = (const float*)d_in[0];
    const int*   ei   = (const int*)  d_in[1];
    const float* ea   = (const float*)d_in[2];
    const float* neW  = (const float*)d_in[3];
    const float* neb  = (const float*)d_in[4];
    const float* neg  = (const float*)d_in[5];
    const float* nebt = (const float*)d_in[6];
    const float* eeW  = (const float*)d_in[7];
    const float* eeb  = (const float*)d_in[8];
    const float* eeg  = (const float*)d_in[9];
    const float* eebt = (const float*)d_in[10];
    const float* Wl   = (const float*)d_in[11];
    const float* bl   = (const float*)d_in[12];
    const float* Wr   = (const float*)d_in[13];
    const float* br   = (const float*)d_in[14];
    const float* We   = (const float*)d_in[15];
    const float* att  = (const float*)d_in[16];
    const float* cb   = (const float*)d_in[17];
    const float* lng  = (const float*)d_in[18];
    const float* lnb  = (const float*)d_in[19];
    const float* W1   = (const float*)d_in[20];
    const float* b1   = (const float*)d_in[21];
    const float* W2   = (const float*)d_in[22];
    const float* b2   = (const float*)d_in[23];
    float* out = (float*)d_out;

    cudaFuncSetAttribute(lin_kernel, cudaFuncAttributeMaxDynamicSharedMemorySize,
                         LIN_SMEM);
    cudaFuncSetAttribute(passA_kernel, cudaFuncAttributeMaxDynamicSharedMemorySize,
                         PASSA_SMEM);

    dim3 lin_grid((NN + LIN_ROWS - 1) / LIN_ROWS, 2);
    int passa_grid = EE / PA_EDGES;

    node_enc_kernel<<<NN / 8, 256>>>(x, neW, neb, neg, nebt);                    // 0
    csr_zero_kernel<<<(NN + 255) / 256, 256>>>();                                // 1
    csr_count_kernel<<<(EE + 255) / 256, 256>>>(ei);                             // 2
    lin_kernel<<<lin_grid, 256, LIN_SMEM>>>(Wl, bl, Wr, br);                     // 3 (profiled)
    csr_scan_kernel<<<1, 1024>>>();                                              // 4
    csr_scatter_kernel<<<(EE + 255) / 256, 256>>>(ei);                           // 5
    edge_enc_kernel<<<EE / 8, 256>>>(ea, eeW, eeb, eeg, eebt);                   // 6 (needs g_slot)

    for (int l = 0; l < LL; l++) {
        if (l > 0)
            lin_kernel<<<lin_grid, 256, LIN_SMEM>>>(Wl + l * DD * DD, bl + l * DD,
                                                    Wr + l * DD * DD, br + l * DD);
        passA_kernel<<<passa_grid, 256, PASSA_SMEM>>>(We + l * EH * DD,
                                                      att + l * HH * CC);
        passB_kernel<<<(NN * 32 + 255) / 256, 256>>>(cb + l * DD, lng + l * DD,
                                                     lnb + l * DD);
    }
    head_kernel<<<NN / 8, 256>>>(out, W1, b1, W2, b2);
}

// round 17
// speedup vs baseline: 1.4505x; 1.0133x over previous
#include <cuda_runtime.h>
#include <math.h>
#include <stdint.h>

#define NN 50000
#define EE 400000
#define DD 128
#define HH 8
#define CC 16
#define EH 64
#define LL 6

static_assert(EE % 128 == 0, "edge tiling");
static_assert(NN % 8 == 0, "node tiling");

typedef unsigned long long u64;

// ---------------- device scratch (static; no allocations allowed) ----------------
__device__ __align__(16) float g_h  [NN * DD];   // node features
__device__ __align__(8) uint32_t g_xlh[NN * 64]; // bf16x2 xl (sole representation)
__device__ __align__(8) uint32_t g_xrh[NN * 64]; // bf16x2 xr (sole representation)
__device__ __align__(16) u64 g_ef2[EE * 16];     // ef, CSR-slot order, bf16 m16n8k16 frags
__device__             float g_a   [EE * HH];    // exp(logit), indexed by CSR SLOT
// CSR by destination node (built once per launch)
__device__ int  g_cnt   [NN];
__device__ int  g_wptr  [NN];
__device__ int  g_rowptr[NN + 1];
__device__ int2 g_csr    [EE];   // (orig edge id, src node) per slot
__device__ int  g_csr_dst[EE];   // dst node per slot
__device__ int  g_slot   [EE];   // edge id -> CSR slot (inverse map)

__device__ __forceinline__ float warp_sum(float v) {
#pragma unroll
    for (int o = 16; o; o >>= 1) v += __shfl_xor_sync(0xffffffffu, v, o);
    return v;
}
__device__ __forceinline__ u64 pack2u(uint32_t lo, uint32_t hi) {
    return ((u64)hi << 32) | (u64)lo;
}
__device__ __forceinline__ uint32_t pack_bf2(float lo, float hi) {
    uint32_t r;
    asm("cvt.rn.bf16x2.f32 %0, %1, %2;" : "=r"(r) : "f"(hi), "f"(lo));
    return r;
}
__device__ __forceinline__ float2 unpack_bf2(uint32_t u) {
    float2 r;
    r.x = __uint_as_float(u << 16);
    r.y = __uint_as_float(u & 0xffff0000u);
    return r;
}

// ---------------- node encoder: x(N,9) -> LN -> relu -> g_h(N,128). 1 warp/node ----
__global__ void node_enc_kernel(const float* __restrict__ x,
                                const float* __restrict__ W,
                                const float* __restrict__ b,
                                const float* __restrict__ g,
                                const float* __restrict__ beta) {
    int warp = (blockIdx.x * blockDim.x + threadIdx.x) >> 5;
    int lane = threadIdx.x & 31;
    if (warp >= NN) return;
    float acc[4];
#pragma unroll
    for (int j = 0; j < 4; j++) acc[j] = b[lane + 32 * j];
#pragma unroll
    for (int k = 0; k < 9; k++) {
        float xv = x[warp * 9 + k];
#pragma unroll
        for (int j = 0; j < 4; j++) acc[j] += xv * W[k * DD + lane + 32 * j];
    }
    float s = 0.f;
#pragma unroll
    for (int j = 0; j < 4; j++) s += acc[j];
    float m = warp_sum(s) * (1.0f / DD);
    float v = 0.f;
#pragma unroll
    for (int j = 0; j < 4; j++) { float d = acc[j] - m; v += d * d; }
    v = warp_sum(v) * (1.0f / DD);
    float rstd = rsqrtf(v + 1e-5f);
#pragma unroll
    for (int j = 0; j < 4; j++) {
        int d = lane + 32 * j;
        float y = (acc[j] - m) * rstd * g[d] + beta[d];
        g_h[warp * DD + d] = fmaxf(y, 0.0f);
    }
}

// ---------------- edge encoder -> g_ef2[slot], bf16 m16n8k16 fragment layout -------
__global__ void edge_enc_kernel(const float* __restrict__ ea,
                                const float* __restrict__ W,
                                const float* __restrict__ b,
                                const float* __restrict__ g,
                                const float* __restrict__ beta) {
    int warp = (blockIdx.x * blockDim.x + threadIdx.x) >> 5;
    int lane = threadIdx.x & 31;
    if (warp >= EE) return;
    float a0 = b[lane], a1 = b[lane + 32];
#pragma unroll
    for (int k = 0; k < 3; k++) {
        float xv = ea[warp * 3 + k];
        a0 += xv * W[k * EH + lane];
        a1 += xv * W[k * EH + 32 + lane];
    }
    float m = warp_sum(a0 + a1) * (1.0f / EH);
    float d0v = a0 - m, d1v = a1 - m;
    float v = warp_sum(d0v * d0v + d1v * d1v) * (1.0f / EH);
    float rstd = rsqrtf(v + 1e-5f);
    float y0 = fmaxf(d0v * rstd * g[lane] + beta[lane], 0.f);
    float y1 = fmaxf(d1v * rstd * g[lane + 32] + beta[lane + 32], 0.f);

    int L = lane & 15;
    int gk = L >> 2, q = L & 3;
    int d0 = gk * 16 + 2 * q;
    int d1 = d0 + 1, d2 = d0 + 8, d3 = d0 + 9;
    float s0a = __shfl_sync(0xffffffffu, y0, d0 & 31);
    float s0b = __shfl_sync(0xffffffffu, y1, d0 & 31);
    float s1a = __shfl_sync(0xffffffffu, y0, d1 & 31);
    float s1b = __shfl_sync(0xffffffffu, y1, d1 & 31);
    float s2a = __shfl_sync(0xffffffffu, y0, d2 & 31);
    float s2b = __shfl_sync(0xffffffffu, y1, d2 & 31);
    float s3a = __shfl_sync(0xffffffffu, y0, d3 & 31);
    float s3b = __shfl_sync(0xffffffffu, y1, d3 & 31);
    if (lane < 16) {
        float v0 = (d0 < 32) ? s0a : s0b;
        float v1 = (d1 < 32) ? s1a : s1b;
        float v2 = (d2 < 32) ? s2a : s2b;
        float v3 = (d3 < 32) ? s3a : s3b;
        int slot = g_slot[warp];
        g_ef2[(size_t)slot * 16 + L] =
            pack2u(pack_bf2(v0, v1), pack_bf2(v2, v3));
    }
}

// ---------------- CSR build (once per launch) --------------------------------------
__global__ void csr_zero_kernel() {
    int i = blockIdx.x * blockDim.x + threadIdx.x;
    if (i < NN) g_cnt[i] = 0;
}
__global__ void csr_count_kernel(const int* __restrict__ ei) {
    int e = blockIdx.x * blockDim.x + threadIdx.x;
    if (e < EE) atomicAdd(&g_cnt[ei[EE + e]], 1);
}
__global__ void csr_scan_kernel() {
    __shared__ int warpsum[32];
    __shared__ int s_total;
    int tid = threadIdx.x, lane = tid & 31, wid = tid >> 5;
    if (tid == 0) { s_total = 0; g_rowptr[0] = 0; }
    __syncthreads();
    for (int base = 0; base < NN; base += 1024) {
        int i = base + tid;
        int v = (i < NN) ? g_cnt[i] : 0;
        int x = v;
#pragma unroll
        for (int o = 1; o < 32; o <<= 1) {
            int t = __shfl_up_sync(0xffffffffu, x, o);
            if (lane >= o) x += t;
        }
        if (lane == 31) warpsum[wid] = x;
        __syncthreads();
        if (wid == 0) {
            int w = warpsum[lane];
#pragma unroll
            for (int o = 1; o < 32; o <<= 1) {
                int t = __shfl_up_sync(0xffffffffu, w, o);
                if (lane >= o) w += t;
            }
            warpsum[lane] = w;
        }
        __syncthreads();
        int incl = s_total + (wid ? warpsum[wid - 1] : 0) + x;
        if (i < NN) {
            g_rowptr[i + 1] = incl;
            g_wptr[i] = incl - v;
        }
        __syncthreads();
        if (tid == 0) s_total += warpsum[31];
        __syncthreads();
    }
}
__global__ void csr_scatter_kernel(const int* __restrict__ ei) {
    int e = blockIdx.x * blockDim.x + threadIdx.x;
    if (e < EE) {
        int d = ei[EE + e];
        int pos = atomicAdd(&g_wptr[d], 1);
        g_csr[pos] = make_int2(e, ei[e]);
        g_csr_dst[pos] = d;
        g_slot[e] = pos;
    }
}

// ---------------- xl+xr GEMM: one block does BOTH weights (A staged once) ----------
#define LIN_ROWS 64
#define LKSB 36   // u64 stride per row: 32 frags (8 k-groups x 4) + 4 pad
#define LIN_SMEM ((LIN_ROWS + DD) * LKSB * 8)
__global__ __launch_bounds__(256, 3) void lin_kernel(
    const float* __restrict__ Wl, const float* __restrict__ bl,
    const float* __restrict__ Wr, const float* __restrict__ br) {
    extern __shared__ char smem_raw[];
    u64* sA = (u64*)smem_raw;                          // [64 rows][LKSB]
    u64* sW = (u64*)(smem_raw + LIN_ROWS * LKSB * 8);  // [128 n][LKSB]
    int m0 = blockIdx.x * LIN_ROWS;
    int tid = threadIdx.x;

    // stage A once
    for (int idx = tid; idx < LIN_ROWS * (DD / 16); idx += 256) {
        int r = idx >> 3, gk = idx & 7;
        int gm = m0 + r;
        float4 v0 = make_float4(0.f, 0.f, 0.f, 0.f), v1 = v0, v2 = v0, v3 = v0;
        if (gm < NN) {
            const float* hp = &g_h[(size_t)gm * DD + gk * 16];
            v0 = *(const float4*)&hp[0];
            v1 = *(const float4*)&hp[4];
            v2 = *(const float4*)&hp[8];
            v3 = *(const float4*)&hp[12];
        }
        u64* d = sA + r * LKSB + gk * 4;
        d[0] = pack2u(pack_bf2(v0.x, v0.y), pack_bf2(v2.x, v2.y));
        d[1] = pack2u(pack_bf2(v0.z, v0.w), pack_bf2(v2.z, v2.w));
        d[2] = pack2u(pack_bf2(v1.x, v1.y), pack_bf2(v3.x, v3.y));
        d[3] = pack2u(pack_bf2(v1.z, v1.w), pack_bf2(v3.z, v3.w));
    }

    int lane = tid & 31, wm = tid >> 5;
    int gid = lane >> 2, q = lane & 3;
    int row_base = (wm & 3) * 16;
    int n_base = (wm >> 2) * 64;
    int r0 = row_base + gid, r1 = r0 + 8;
    const u64* ar0 = sA + r0 * LKSB;
    const u64* ar1 = sA + r1 * LKSB;
    int gm0 = m0 + r0, gm1 = m0 + r1;

#pragma unroll
    for (int wv = 0; wv < 2; wv++) {
        const float* W  = wv ? Wr : Wl;
        const float* bv = wv ? br : bl;
        uint32_t* dsth = wv ? g_xrh : g_xlh;

        // stage W(wv); barrier first so prior iteration's MMA reads are done
        __syncthreads();
        for (int idx = tid; idx < DD * (DD / 16); idx += 256) {
            int n = idx & 127, gk = idx >> 7;
            float w[16];
#pragma unroll
            for (int j = 0; j < 16; j++) w[j] = W[(gk * 16 + j) * DD + n];
#pragma unroll
            for (int qq = 0; qq < 4; qq++)
                sW[n * LKSB + gk * 4 + qq] =
                    pack2u(pack_bf2(w[2 * qq], w[2 * qq + 1]),
                           pack_bf2(w[2 * qq + 8], w[2 * qq + 9]));
        }
        __syncthreads();

        float d[8][4];
#pragma unroll
        for (int n8 = 0; n8 < 8; n8++)
#pragma unroll
            for (int j = 0; j < 4; j++) d[n8][j] = 0.f;

#pragma unroll
        for (int gk = 0; gk < 8; gk++) {
            u64 pa0 = ar0[gk * 4 + q];
            u64 pa1 = ar1[gk * 4 + q];
            uint32_t a0 = (uint32_t)pa0, a2 = (uint32_t)(pa0 >> 32);
            uint32_t a1 = (uint32_t)pa1, a3 = (uint32_t)(pa1 >> 32);
#pragma unroll
            for (int n8 = 0; n8 < 8; n8++) {
                u64 pb = sW[(n_base + n8 * 8 + gid) * LKSB + gk * 4 + q];
                uint32_t b0 = (uint32_t)pb, b1 = (uint32_t)(pb >> 32);
                asm volatile(
                    "mma.sync.aligned.m16n8k16.row.col.f32.bf16.bf16.f32 "
                    "{%0,%1,%2,%3}, {%4,%5,%6,%7}, {%8,%9}, {%0,%1,%2,%3};"
                    : "+f"(d[n8][0]), "+f"(d[n8][1]), "+f"(d[n8][2]), "+f"(d[n8][3])
                    : "r"(a0), "r"(a1), "r"(a2), "r"(a3), "r"(b0), "r"(b1));
            }
        }

#pragma unroll
        for (int n8 = 0; n8 < 8; n8++) {
            int c = n_base + n8 * 8 + 2 * q;
            float2 bb = *(const float2*)&bv[c];
            if (gm0 < NN)
                dsth[(size_t)gm0 * 64 + (c >> 1)] =
                    pack_bf2(d[n8][0] + bb.x, d[n8][1] + bb.y);
            if (gm1 < NN)
                dsth[(size_t)gm1 * 64 + (c >> 1)] =
                    pack_bf2(d[n8][2] + bb.x, d[n8][3] + bb.y);
        }
    }
}

// ---------------- pass A: bf16 m16n8k16 TC ee GEMM + logits + exp ------------------
#define PA_EDGES 128
#define EFSB 20   // u64 stride per row: 16 frags + 4 pad
#define PASSA_SMEM (PA_EDGES * EFSB * 8 + DD * EFSB * 8 + DD * 4)
__global__ __launch_bounds__(256, 4) void passA_kernel(const float* __restrict__ We,
                                                       const float* __restrict__ att) {
    extern __shared__ char smem_raw[];
    u64*   sEf = (u64*)smem_raw;                            // [128 rows][EFSB]
    u64*   sWe = (u64*)(smem_raw + PA_EDGES * EFSB * 8);    // [128 n][EFSB]
    float* sAtt = (float*)(smem_raw + PA_EDGES * EFSB * 8 + DD * EFSB * 8);
    __shared__ int sSrc[PA_EDGES], sDst[PA_EDGES];
    int tid = threadIdx.x;
    int eb = blockIdx.x * PA_EDGES;

    if (tid < PA_EDGES) {
        sSrc[tid] = g_csr[eb + tid].y;
        sDst[tid] = g_csr_dst[eb + tid];
    }
    if (tid < DD) sAtt[tid] = att[tid];
    for (int idx = tid; idx < DD * (EH / 16); idx += 256) {
        int n = idx & 127, gk = idx >> 7;
        float w[16];
#pragma unroll
        for (int j = 0; j < 16; j++) w[j] = We[(gk * 16 + j) * DD + n];
#pragma unroll
        for (int q = 0; q < 4; q++)
            sWe[n * EFSB + gk * 4 + q] =
                pack2u(pack_bf2(w[2 * q], w[2 * q + 1]),
                       pack_bf2(w[2 * q + 8], w[2 * q + 9]));
    }
    for (int idx = tid; idx < PA_EDGES * 8; idx += 256) {
        int r = idx >> 3, c2 = (idx & 7) << 1;
        uint4 v = *(const uint4*)&g_ef2[(size_t)(eb + r) * 16 + c2];
        *(uint4*)&sEf[r * EFSB + c2] = v;
    }
    __syncthreads();

    int lane = tid & 31, wm = tid >> 5;
    int gid = lane >> 2, q = lane & 3;

    int r0 = wm * 16 + gid;
    int r1 = r0 + 8;
    const uint32_t* xl0h = g_xlh + (size_t)sSrc[r0] * 64;
    const uint32_t* xr0h = g_xrh + (size_t)sDst[r0] * 64;
    const uint32_t* xl1h = g_xlh + (size_t)sSrc[r1] * 64;
    const uint32_t* xr1h = g_xrh + (size_t)sDst[r1] * 64;

    u64 A0[4], A1[4];
    {
        const u64* efr0 = sEf + r0 * EFSB;
        const u64* efr1 = sEf + r1 * EFSB;
#pragma unroll
        for (int gk = 0; gk < 4; gk++) {
            A0[gk] = efr0[gk * 4 + q];
            A1[gk] = efr1[gk * 4 + q];
        }
    }

    float h0[8], h1[8];
#pragma unroll
    for (int h = 0; h < 8; h++) { h0[h] = 0.f; h1[h] = 0.f; }

#pragma unroll
    for (int half = 0; half < 2; half++) {
        float d[8][4];
#pragma unroll
        for (int n8 = 0; n8 < 8; n8++)
#pragma unroll
            for (int j = 0; j < 4; j++) d[n8][j] = 0.f;

#pragma unroll
        for (int gk = 0; gk < 4; gk++) {
            uint32_t a0 = (uint32_t)A0[gk], a2 = (uint32_t)(A0[gk] >> 32);
            uint32_t a1 = (uint32_t)A1[gk], a3 = (uint32_t)(A1[gk] >> 32);
#pragma unroll
            for (int n8 = 0; n8 < 8; n8++) {
                int n = half * 8 + n8;
                u64 pb = sWe[(n * 8 + gid) * EFSB + gk * 4 + q];
                uint32_t b0 = (uint32_t)pb, b1 = (uint32_t)(pb >> 32);
                asm volatile(
                    "mma.sync.aligned.m16n8k16.row.col.f32.bf16.bf16.f32 "
                    "{%0,%1,%2,%3}, {%4,%5,%6,%7}, {%8,%9}, {%0,%1,%2,%3};"
                    : "+f"(d[n8][0]), "+f"(d[n8][1]), "+f"(d[n8][2]), "+f"(d[n8][3])
                    : "r"(a0), "r"(a1), "r"(a2), "r"(a3), "r"(b0), "r"(b1));
            }
        }
#pragma unroll
        for (int n8 = 0; n8 < 8; n8++) {
            int n = half * 8 + n8;
            int ci = n * 4 + q;
            float2 av = *(const float2*)&sAtt[n * 8 + q * 2];
            float2 l0v = unpack_bf2(xl0h[ci]);
            float2 r0v = unpack_bf2(xr0h[ci]);
            float2 l1v = unpack_bf2(xl1h[ci]);
            float2 r1v = unpack_bf2(xr1h[ci]);
            float v00 = d[n8][0] + l0v.x + r0v.x; v00 = v00 > 0.f ? v00 : 0.2f * v00;
            float v01 = d[n8][1] + l0v.y + r0v.y; v01 = v01 > 0.f ? v01 : 0.2f * v01;
            float v10 = d[n8][2] + l1v.x + r1v.x; v10 = v10 > 0.f ? v10 : 0.2f * v10;
            float v11 = d[n8][3] + l1v.y + r1v.y; v11 = v11 > 0.f ? v11 : 0.2f * v11;
            h0[n >> 1] += v00 * av.x + v01 * av.y;
            h1[n >> 1] += v10 * av.x + v11 * av.y;
        }
    }
#pragma unroll
    for (int h = 0; h < 8; h++) {
        h0[h] += __shfl_xor_sync(0xffffffffu, h0[h], 1);
        h0[h] += __shfl_xor_sync(0xffffffffu, h0[h], 2);
        h1[h] += __shfl_xor_sync(0xffffffffu, h1[h], 1);
        h1[h] += __shfl_xor_sync(0xffffffffu, h1[h], 2);
    }
    size_t p0 = (size_t)(eb + r0) * HH;
    size_t p1 = (size_t)(eb + r1) * HH;
    g_a[p0 + 2 * q]     = expf(h0[2 * q]);
    g_a[p0 + 2 * q + 1] = expf(h0[2 * q + 1]);
    g_a[p1 + 2 * q]     = expf(h1[2 * q]);
    g_a[p1 + 2 * q + 1] = expf(h1[2 * q + 1]);
}

// ---------------- pass B: per-dst gather (bf16 xl), 8-way MLP, residual+LN+relu ----
__global__ __launch_bounds__(256) void passB_kernel(const float* __restrict__ cb,
                                                    const float* __restrict__ g,
                                                    const float* __restrict__ beta) {
    int node = (blockIdx.x * blockDim.x + threadIdx.x) >> 5;
    int lane = threadIdx.x & 31;
    if (node >= NN) return;
    int start = g_rowptr[node], end = g_rowptr[node + 1];

    float s = 0.f;
    for (int p0 = start; p0 < end; p0 += 4) {
        int p = p0 + (lane >> 3);
        if (p < end) s += g_a[(size_t)p * HH + (lane & 7)];
    }
    s += __shfl_xor_sync(0xffffffffu, s, 8);
    s += __shfl_xor_sync(0xffffffffu, s, 16);
    float sh = __shfl_sync(0xffffffffu, s, lane >> 2);
    float rinv = 1.0f / (sh + 1e-16f);

    int head = lane >> 2;
    float4 acc = make_float4(0.f, 0.f, 0.f, 0.f);
    int p = start;
    for (; p + 8 <= end; p += 8) {
        int sn[8]; float al[8]; uint2 uu[8];
#pragma unroll
        for (int j = 0; j < 8; j++) sn[j] = g_csr[p + j].y;
#pragma unroll
        for (int j = 0; j < 8; j++) al[j] = g_a[(size_t)(p + j) * HH + head];
#pragma unroll
        for (int j = 0; j < 8; j++)
            uu[j] = *(const uint2*)&g_xlh[(size_t)sn[j] * 64 + 2 * lane];
#pragma unroll
        for (int j = 0; j < 8; j++) {
            float2 xa = unpack_bf2(uu[j].x), xb = unpack_bf2(uu[j].y);
            acc.x += al[j] * xa.x; acc.y += al[j] * xa.y;
            acc.z += al[j] * xb.x; acc.w += al[j] * xb.y;
        }
    }
    for (; p + 4 <= end; p += 4) {
        int sn[4]; float al[4]; uint2 uu[4];
#pragma unroll
        for (int j = 0; j < 4; j++) sn[j] = g_csr[p + j].y;
#pragma unroll
        for (int j = 0; j < 4; j++) al[j] = g_a[(size_t)(p + j) * HH + head];
#pragma unroll
        for (int j = 0; j < 4; j++)
            uu[j] = *(const uint2*)&g_xlh[(size_t)sn[j] * 64 + 2 * lane];
#pragma unroll
        for (int j = 0; j < 4; j++) {
            float2 xa = unpack_bf2(uu[j].x), xb = unpack_bf2(uu[j].y);
            acc.x += al[j] * xa.x; acc.y += al[j] * xa.y;
            acc.z += al[j] * xb.x; acc.w += al[j] * xb.y;
        }
    }
    for (; p < end; p++) {
        int sn = g_csr[p].y;
        float al = g_a[(size_t)p * HH + head];
        uint2 u = *(const uint2*)&g_xlh[(size_t)sn * 64 + 2 * lane];
        float2 xa = unpack_bf2(u.x), xb = unpack_bf2(u.y);
        acc.x += al * xa.x; acc.y += al * xa.y;
        acc.z += al * xb.x; acc.w += al * xb.y;
    }
    acc.x *= rinv; acc.y *= rinv; acc.z *= rinv; acc.w *= rinv;

    int d0 = 4 * lane;
    float4 hv = *(const float4*)&g_h[node * DD + d0];
    float4 cv = *(const float4*)&cb[d0];
    float a0 = acc.x + cv.x + hv.x;
    float a1 = acc.y + cv.y + hv.y;
    float a2 = acc.z + cv.z + hv.z;
    float a3 = acc.w + cv.w + hv.w;
    float m = warp_sum(a0 + a1 + a2 + a3) * (1.0f / DD);
    float e0d = a0 - m, e1d = a1 - m, e2d = a2 - m, e3d = a3 - m;
    float v = warp_sum(e0d * e0d + e1d * e1d + e2d * e2d + e3d * e3d) * (1.0f / DD);
    float rstd = rsqrtf(v + 1e-5f);
    float4 gv = *(const float4*)&g[d0];
    float4 bv = *(const float4*)&beta[d0];
    float4 o;
    o.x = fmaxf(e0d * rstd * gv.x + bv.x, 0.f);
    o.y = fmaxf(e1d * rstd * gv.y + bv.y, 0.f);
    o.z = fmaxf(e2d * rstd * gv.z + bv.z, 0.f);
    o.w = fmaxf(e3d * rstd * gv.w + bv.w, 0.f);
    *(float4*)&g_h[node * DD + d0] = o;
}

// ---------------- head: relu(h@W1+b1) @ W2 -> sigmoid. 1 warp/node -----------------
__global__ void head_kernel(float* __restrict__ out,
                            const float* __restrict__ W1, const float* __restrict__ b1,
                            const float* __restrict__ W2, const float* __restrict__ b2) {
    int warp = (blockIdx.x * blockDim.x + threadIdx.x) >> 5;
    int lane = threadIdx.x & 31;
    if (warp >= NN) return;
    float hr[4];
#pragma unroll
    for (int q = 0; q < 4; q++) hr[q] = g_h[warp * DD + q * 32 + lane];
    float z0 = b1[lane], z1 = b1[lane + 32];
#pragma unroll
    for (int q = 0; q < 4; q++) {
#pragma unroll 8
        for (int kk = 0; kk < 32; kk++) {
            float hk = __shfl_sync(0xffffffffu, hr[q], kk);
            int k = q * 32 + kk;
            z0 += hk * W1[k * 64 + lane];
            z1 += hk * W1[k * 64 + 32 + lane];
        }
    }
    z0 = fmaxf(z0, 0.f);
    z1 = fmaxf(z1, 0.f);
    float p = z0 * W2[lane] + z1 * W2[lane + 32];
    p = warp_sum(p);
    if (lane == 0) out[warp] = 1.0f / (1.0f + expf(-(p + b2[0])));
}

// ---------------- launch ----------------------------------------------------------
extern "C" void kernel_launch(void* const* d_in, const int* in_sizes, int n_in,
                              void* d_out, int out_size) {
    const float* x    = (const float*)d_in[0];
    const int*   ei   = (const int*)  d_in[1];
    const float* ea   = (const float*)d_in[2];
    const float* neW  = (const float*)d_in[3];
    const float* neb  = (const float*)d_in[4];
    const float* neg  = (const float*)d_in[5];
    const float* nebt = (const float*)d_in[6];
    const float* eeW  = (const float*)d_in[7];
    const float* eeb  = (const float*)d_in[8];
    const float* eeg  = (const float*)d_in[9];
    const float* eebt = (const float*)d_in[10];
    const float* Wl   = (const float*)d_in[11];
    const float* bl   = (const float*)d_in[12];
    const float* Wr   = (const float*)d_in[13];
    const float* br   = (const float*)d_in[14];
    const float* We   = (const float*)d_in[15];
    const float* att  = (const float*)d_in[16];
    const float* cb   = (const float*)d_in[17];
    const float* lng  = (const float*)d_in[18];
    const float* lnb  = (const float*)d_in[19];
    const float* W1   = (const float*)d_in[20];
    const float* b1   = (const float*)d_in[21];
    const float* W2   = (const float*)d_in[22];
    const float* b2   = (const float*)d_in[23];
    float* out = (float*)d_out;

    cudaFuncSetAttribute(lin_kernel, cudaFuncAttributeMaxDynamicSharedMemorySize,
                         LIN_SMEM);
    cudaFuncSetAttribute(passA_kernel, cudaFuncAttributeMaxDynamicSharedMemorySize,
                         PASSA_SMEM);

    int lin_grid = (NN + LIN_ROWS - 1) / LIN_ROWS;   // 782, both weights per block
    int passa_grid = EE / PA_EDGES;

    node_enc_kernel<<<NN / 8, 256>>>(x, neW, neb, neg, nebt);                    // 0
    csr_zero_kernel<<<(NN + 255) / 256, 256>>>();                                // 1
    csr_count_kernel<<<(EE + 255) / 256, 256>>>(ei);                             // 2
    lin_kernel<<<lin_grid, 256, LIN_SMEM>>>(Wl, bl, Wr, br);                     // 3 (profiled)
    csr_scan_kernel<<<1, 1024>>>();                                              // 4
    csr_scatter_kernel<<<(EE + 255) / 256, 256>>>(ei);                           // 5
    edge_enc_kernel<<<EE / 8, 256>>>(ea, eeW, eeb, eeg, eebt);                   // 6 (needs g_slot)

    for (int l = 0; l < LL; l++) {
        if (l > 0)
            lin_kernel<<<lin_grid, 256, LIN_SMEM>>>(Wl + l * DD * DD, bl + l * DD,
                                                    Wr + l * DD * DD, br + l * DD);
        passA_kernel<<<passa_grid, 256, PASSA_SMEM>>>(We + l * EH * DD,
                                                      att + l * HH * CC);
        passB_kernel<<<(NN * 32 + 255) / 256, 256>>>(cb + l * DD, lng + l * DD,
                                                     lnb + l * DD);
    }
    head_kernel<<<NN / 8, 256>>>(out, W1, b1, W2, b2);
}